// round 8
// baseline (speedup 1.0000x reference)
#include <cuda_runtime.h>
#include <cuda_bf16.h>

// ---------------------------------------------------------------------------
// DPSOM fused kernel, round 8 (= R7 resubmitted; R7 hit GPUAcquisitionTimeout
// and never ran).
// vs R6 (628us; main 436us tensor=31% L1=58%, regs capped at 128/512thr):
//  * 256 threads/CTA, 8 warps, warp tile 64x64 (acc=128 regs/thread, now
//    legal; R6's 512x128 = whole RF). B ldsm reuse doubled, ILP doubled.
//  * GUARD 4e-3 -> 5e-4 (>=15x over measured delta-d bound) to cut the
//    repair-kernel tail (~190us of the R6 total was outside the main kernel).
// B-fragment lane mapping identical to proven R6 code.
//   output layout: [x_recon (B*784) | z (B*32) | som_z (B*32)]  (fp32)
// ---------------------------------------------------------------------------

#define BATCH   65536
#define K1      784
#define HID     256
#define LAT     32
#define NPROTO  25
#define BM      128
#define NTHR    256
#define NCH     13            // 13 x 64 = 832 >= 784, tail zero-padded
#define GUARD   5e-4f

// smem (bytes): [0..1024) be1 staging; [1024 + st*98304) stages:
//   A_hi 16KB | A_lo 16KB | B_hi 32KB | B_lo 32KB
// epilogue aliases stages after mainloop.
#define STG_BYTES  98304
#define HS_OFF     256                           // floats
#define HSTRIDE    257
#define EP_WE2     (HS_OFF + BM * HSTRIDE)       // 33152
#define EP_ZS      (EP_WE2 + HID * LAT)          // 41344
#define EP_DS      (EP_ZS + BM * LAT)            // 45440
#define EP_PROTO   (EP_DS + BM * NPROTO)         // 48640
#define EP_PN      (EP_PROTO + NPROTO * LAT)     // 49440
#define EP_ZZ      (EP_PN + 32)                  // 49472
#define EP_WIN     (EP_ZZ + BM)                  // 49600
#define SMEM_FLOATS (EP_WIN + BM)                // 49728
#define SMEM_BYTES  (SMEM_FLOATS * 4)            // 198912

typedef unsigned long long u64;
typedef unsigned int u32;

// W pre-converted + pre-swizzled [n][k] tiles: [chunk][32KB image]
__device__ uint4 g_Bhi[NCH * 2048];
__device__ uint4 g_Blo[NCH * 2048];
__device__ float4 g_recon_table4[NPROTO * (K1 / 4)];
__device__ int    g_repair_count;
__device__ int    g_repair_rows[BATCH];

__host__ __device__ __forceinline__ u32 swz(u32 b) { return b ^ ((b >> 3) & 0x70); }

__device__ __forceinline__ u32 su(const void* p) {
    u32 a;
    asm("{ .reg .u64 t; cvta.to.shared.u64 t, %1; cvt.u32.u64 %0, t; }" : "=r"(a) : "l"(p));
    return a;
}
__device__ __forceinline__ void ldsm4(u32 a, u32& r0, u32& r1, u32& r2, u32& r3) {
    asm volatile("ldmatrix.sync.aligned.m8n8.x4.shared.b16 {%0,%1,%2,%3}, [%4];"
                 : "=r"(r0), "=r"(r1), "=r"(r2), "=r"(r3) : "r"(a));
}
__device__ __forceinline__ void mma16816(float* c, const u32* a, u32 b0, u32 b1) {
    asm volatile("mma.sync.aligned.m16n8k16.row.col.f32.bf16.bf16.f32 "
                 "{%0,%1,%2,%3},{%4,%5,%6,%7},{%8,%9},{%0,%1,%2,%3};"
                 : "+f"(c[0]), "+f"(c[1]), "+f"(c[2]), "+f"(c[3])
                 : "r"(a[0]), "r"(a[1]), "r"(a[2]), "r"(a[3]), "r"(b0), "r"(b1));
}
__device__ __forceinline__ void cpasync16(u32 dst, const void* src) {
    asm volatile("cp.async.cg.shared.global [%0], [%1], 16;" :: "r"(dst), "l"(src));
}
#define CP_COMMIT() asm volatile("cp.async.commit_group;")
#define CP_WAIT0()  asm volatile("cp.async.wait_group 0;")

// ---------------- prep kernels ----------------
__global__ void zero_flags_kernel() { g_repair_count = 0; }

__global__ void prep_w_kernel(const float* __restrict__ We1) {
    const int c = blockIdx.x;
    __nv_bfloat16* bh = (__nv_bfloat16*)g_Bhi;
    __nv_bfloat16* bl = (__nv_bfloat16*)g_Blo;
    for (int idx = threadIdx.x; idx < 256 * 64; idx += blockDim.x) {
        int n = idx >> 6, kp = idx & 63;
        int k = c * 64 + kp;
        float v = (k < K1) ? We1[k * HID + n] : 0.0f;
        __nv_bfloat16 hi = __float2bfloat16(v);
        __nv_bfloat16 lo = __float2bfloat16(v - __bfloat162float(hi));
        u32 off = (u32)c * 32768u + swz((u32)n * 128u + (u32)kp * 2u);
        bh[off >> 1] = hi;
        bl[off >> 1] = lo;
    }
}

__global__ void decoder_table_kernel(const float* __restrict__ Wd1,
                                     const float* __restrict__ bd1,
                                     const float* __restrict__ Wd2,
                                     const float* __restrict__ bd2,
                                     const float* __restrict__ proto) {
    __shared__ float p[LAT];
    __shared__ float hd[HID];
    const int pid = blockIdx.x;
    const int t = threadIdx.x;
    if (t < LAT) p[t] = proto[pid * LAT + t];
    __syncthreads();
    if (t < HID) {
        float acc = 0.0f;
#pragma unroll
        for (int l = 0; l < LAT; l++) acc = fmaf(p[l], Wd1[l * HID + t], acc);
        hd[t] = fmaxf(acc + bd1[t], 0.0f);
    }
    __syncthreads();
    float* gt = (float*)g_recon_table4;
    for (int o = t; o < K1; o += 256) {
        float acc = 0.0f;
#pragma unroll 8
        for (int n = 0; n < HID; n++) acc = fmaf(hd[n], Wd2[n * K1 + o], acc);
        float v = acc + bd2[o];
        gt[pid * K1 + o] = 1.0f / (1.0f + expf(-v));
    }
}

// ---------------- main kernel ----------------
__global__ void __launch_bounds__(NTHR)
dpsom_main_kernel(const float* __restrict__ x,
                  const float* __restrict__ be1,
                  const float* __restrict__ We2,
                  const float* __restrict__ be2,
                  const float* __restrict__ proto,
                  float* __restrict__ out) {
    extern __shared__ float sm[];
    const u32 sb = su(sm);
    const int t = threadIdx.x, lane = t & 31, w = t >> 5;
    const int wr = w >> 2, wc = w & 3;          // warp grid 2 (rows) x 4 (cols)
    const size_t row0 = (size_t)blockIdx.x * BM;

    // A loader role: row ar (0..127), k-half aq (32 k each)
    const int ar = t >> 1, aq = t & 1;
    // B fragment lane decode (proven R6 mapping)
    const u32 bn  = (u32)((lane & 7) + ((lane & 16) ? 8 : 0));
    const u32 bkb = (u32)(((lane >> 3) & 1) * 16);

    sm[t] = be1[t];   // be1 staging (floats 0..255; stages start at byte 1024)

    float4 va[8];
    auto loadA = [&](int c) {
        const float4* xp = (const float4*)(x + (row0 + ar) * K1 + c * 64 + aq * 32);
#pragma unroll
        for (int j = 0; j < 8; j++) {
            int kk = c * 64 + aq * 32 + j * 4;
            float4 v = make_float4(0.f, 0.f, 0.f, 0.f);
            if (kk < K1) v = xp[j];
            va[j] = v;
        }
    };
    auto storeA = [&](int st) {
        char* Sb = (char*)sm + 1024 + st * STG_BYTES;
#pragma unroll
        for (int j = 0; j < 8; j++) {
            float4 v = va[j];
            __nv_bfloat16 hx = __float2bfloat16(v.x), hy = __float2bfloat16(v.y);
            __nv_bfloat16 hz = __float2bfloat16(v.z), hw = __float2bfloat16(v.w);
            __nv_bfloat16 lx = __float2bfloat16(v.x - __bfloat162float(hx));
            __nv_bfloat16 ly = __float2bfloat16(v.y - __bfloat162float(hy));
            __nv_bfloat16 lz = __float2bfloat16(v.z - __bfloat162float(hz));
            __nv_bfloat16 lw = __float2bfloat16(v.w - __bfloat162float(hw));
            uint2 hv, lv;
            hv.x = (u32)__bfloat16_as_ushort(hx) | ((u32)__bfloat16_as_ushort(hy) << 16);
            hv.y = (u32)__bfloat16_as_ushort(hz) | ((u32)__bfloat16_as_ushort(hw) << 16);
            lv.x = (u32)__bfloat16_as_ushort(lx) | ((u32)__bfloat16_as_ushort(ly) << 16);
            lv.y = (u32)__bfloat16_as_ushort(lz) | ((u32)__bfloat16_as_ushort(lw) << 16);
            u32 o = swz((u32)ar * 128u + (u32)((aq * 32 + j * 4) * 2));
            *(uint2*)(Sb + o)         = hv;
            *(uint2*)(Sb + 16384 + o) = lv;
        }
    };
    auto loadB = [&](int c, int st) {
        const uint4* gh = g_Bhi + c * 2048;
        const uint4* gl = g_Blo + c * 2048;
        u32 dh = sb + 1024 + st * STG_BYTES + 32768;
        u32 dl = dh + 32768;
#pragma unroll
        for (int j = 0; j < 8; j++) {
            int o = j * NTHR + t;
            cpasync16(dh + o * 16, gh + o);
            cpasync16(dl + o * 16, gl + o);
        }
        CP_COMMIT();
    };

    // ---- prologue ----
    loadA(0); storeA(0); loadB(0, 0);
    CP_WAIT0();
    __syncthreads();

    float acc[4][8][4];
#pragma unroll
    for (int m = 0; m < 4; m++)
#pragma unroll
        for (int n = 0; n < 8; n++)
#pragma unroll
            for (int q = 0; q < 4; q++) acc[m][n][q] = 0.0f;

#pragma unroll 1
    for (int c = 0; c < NCH; c++) {
        const int st = c & 1;
        if (c + 1 < NCH) { loadB(c + 1, st ^ 1); loadA(c + 1); }

        const u32 SB  = sb + 1024 + st * STG_BYTES;
        const u32 Ahi = SB, Alo = SB + 16384, Bhi = SB + 32768, Blo = SB + 65536;
        const u32 arow = (u32)((wr * 64 + (lane & 15)) * 128) + ((u32)(lane >> 4) << 4);
#pragma unroll
        for (int ks = 0; ks < 4; ks++) {
            const u32 kb = (u32)ks * 32u;
            u32 ah[16], al[16];
#pragma unroll
            for (int m = 0; m < 4; m++) {
                u32 o = arow + (u32)m * 2048u + kb;
                ldsm4(Ahi + swz(o), ah[m*4+0], ah[m*4+1], ah[m*4+2], ah[m*4+3]);
                ldsm4(Alo + swz(o), al[m*4+0], al[m*4+1], al[m*4+2], al[m*4+3]);
            }
#pragma unroll
            for (int half = 0; half < 2; half++) {
                u32 bh[8], bl[8];
#pragma unroll
                for (int pr = 0; pr < 2; pr++) {
                    u32 o = (u32)((wc * 64 + half * 32 + pr * 16 + bn) * 128) + kb + bkb;
                    ldsm4(Bhi + swz(o), bh[pr*4+0], bh[pr*4+1], bh[pr*4+2], bh[pr*4+3]);
                    ldsm4(Blo + swz(o), bl[pr*4+0], bl[pr*4+1], bl[pr*4+2], bl[pr*4+3]);
                }
#pragma unroll
                for (int m = 0; m < 4; m++)
#pragma unroll
                    for (int nt = 0; nt < 4; nt++) {
                        float* cc = acc[m][half * 4 + nt];
                        u32 b0 = bh[(nt >> 1) * 4 + (nt & 1) * 2];
                        u32 b1 = bh[(nt >> 1) * 4 + (nt & 1) * 2 + 1];
                        u32 c0 = bl[(nt >> 1) * 4 + (nt & 1) * 2];
                        u32 c1 = bl[(nt >> 1) * 4 + (nt & 1) * 2 + 1];
                        mma16816(cc, &ah[m * 4], b0, b1);
                        mma16816(cc, &ah[m * 4], c0, c1);
                        mma16816(cc, &al[m * 4], b0, b1);
                    }
            }
        }
        if (c + 1 < NCH) storeA(st ^ 1);
        CP_WAIT0();
        __syncthreads();
    }

    // ---- h = relu(acc + be1) -> hS ----
    float* hS = sm + HS_OFF;
    {
        const int g = lane >> 2, tq = (lane & 3) * 2;
#pragma unroll
        for (int m = 0; m < 4; m++)
#pragma unroll
            for (int nt = 0; nt < 8; nt++) {
                int row = wr * 64 + m * 16 + g;
                int col = wc * 64 + nt * 8 + tq;
                float b0 = sm[col], b1 = sm[col + 1];
                float* cc = acc[m][nt];
                hS[row * HSTRIDE + col]           = fmaxf(cc[0] + b0, 0.0f);
                hS[row * HSTRIDE + col + 1]       = fmaxf(cc[1] + b1, 0.0f);
                hS[(row + 8) * HSTRIDE + col]     = fmaxf(cc[2] + b0, 0.0f);
                hS[(row + 8) * HSTRIDE + col + 1] = fmaxf(cc[3] + b1, 0.0f);
            }
    }
    float* we2s = sm + EP_WE2;
    float* zsS  = sm + EP_ZS;
    float* dsS  = sm + EP_DS;
    float* prS  = sm + EP_PROTO;
    float* pnS  = sm + EP_PN;
    float* zzS  = sm + EP_ZZ;
    int*   winS = (int*)(sm + EP_WIN);
    for (int i = t; i < HID * LAT; i += NTHR) we2s[i] = We2[i];
    for (int i = t; i < NPROTO * LAT; i += NTHR) prS[i] = proto[i];
    __syncthreads();

    // ---- GEMM2 (fp32, R4 order): 2 reps x (row r, 8 lat cols) ----
    {
        float* out_z = out + (size_t)BATCH * K1;
#pragma unroll
        for (int rep = 0; rep < 2; rep++) {
            const int r = rep * 64 + (t >> 2);
            const int latb = (t & 3) * 8;
            u64 a0 = 0, a1 = 0, a2 = 0, a3 = 0;
            const float* hr = hS + r * HSTRIDE;
            const float* wbase = we2s + latb;
#pragma unroll 8
            for (int n = 0; n < HID; n++) {
                float hv = hr[n];
                u64 hd;
                asm("mov.b64 %0,{%1,%1};" : "=l"(hd) : "f"(hv));
                ulonglong2 w0 = *(const ulonglong2*)(wbase + n * LAT);
                ulonglong2 w1 = *(const ulonglong2*)(wbase + n * LAT + 4);
                asm("fma.rn.f32x2 %0, %1, %2, %0;" : "+l"(a0) : "l"(hd), "l"(w0.x));
                asm("fma.rn.f32x2 %0, %1, %2, %0;" : "+l"(a1) : "l"(hd), "l"(w0.y));
                asm("fma.rn.f32x2 %0, %1, %2, %0;" : "+l"(a2) : "l"(hd), "l"(w1.x));
                asm("fma.rn.f32x2 %0, %1, %2, %0;" : "+l"(a3) : "l"(hd), "l"(w1.y));
            }
            float z[8];
            asm("mov.b64 {%0,%1},%2;" : "=f"(z[0]), "=f"(z[1]) : "l"(a0));
            asm("mov.b64 {%0,%1},%2;" : "=f"(z[2]), "=f"(z[3]) : "l"(a1));
            asm("mov.b64 {%0,%1},%2;" : "=f"(z[4]), "=f"(z[5]) : "l"(a2));
            asm("mov.b64 {%0,%1},%2;" : "=f"(z[6]), "=f"(z[7]) : "l"(a3));
            float bz[8];
            *(float4*)bz       = *(const float4*)(be2 + latb);
            *(float4*)(bz + 4) = *(const float4*)(be2 + latb + 4);
#pragma unroll
            for (int j = 0; j < 8; j++) z[j] += bz[j];
            *(float4*)(zsS + r * LAT + latb)     = *(float4*)z;
            *(float4*)(zsS + r * LAT + latb + 4) = *(float4*)(z + 4);
            *(float4*)(out_z + (row0 + r) * LAT + latb)     = *(float4*)z;
            *(float4*)(out_z + (row0 + r) * LAT + latb + 4) = *(float4*)(z + 4);
        }
    }
    __syncthreads();

    // ---- pp (shuffle-tree order), zz, distances (reference form) ----
    if (t < NPROTO) {
        const float* pj = prS + t * LAT;
        float a[32];
#pragma unroll
        for (int l = 0; l < 32; l++) a[l] = pj[l] * pj[l];
#pragma unroll
        for (int off = 16; off >= 1; off >>= 1)
#pragma unroll
            for (int i = 0; i < 16; i++)
                if (i < off) a[i] += a[i + off];
        pnS[t] = a[0];
    }
    if (t >= 128) {
        int rr = t - 128;
        const float* zr = zsS + rr * LAT;
        float s = 0.0f;
#pragma unroll
        for (int l = 0; l < LAT; l++) s = fmaf(zr[l], zr[l], s);
        zzS[rr] = s;
    }
    __syncthreads();
    for (int idx = t; idx < BM * NPROTO; idx += NTHR) {
        int rr = idx / NPROTO;
        int j  = idx - rr * NPROTO;
        const float* zr = zsS + rr * LAT;
        const float* pj = prS + j * LAT;
        float dot = 0.0f;
#pragma unroll
        for (int l = 0; l < LAT; l++) dot = fmaf(zr[l], pj[l], dot);
        dsS[idx] = (zzS[rr] - 2.0f * dot) + pnS[j];
    }
    __syncthreads();

    // ---- argmin + gap guard -> repair list ----
    if (t < BM) {
        const float* dr = dsS + t * NPROTO;
        float best = dr[0], sec = 3.4e38f;
        int bi = 0;
#pragma unroll
        for (int j = 1; j < NPROTO; j++) {
            float v = dr[j];
            if (v < best) { sec = best; best = v; bi = j; }
            else if (v < sec) sec = v;
        }
        winS[t] = bi;
        if (sec - best < GUARD) {
            int idx = atomicAdd(&g_repair_count, 1);
            if (idx < BATCH) g_repair_rows[idx] = (int)(row0 + t);
        }
    }
    __syncthreads();

    // ---- som_z + x_recon (provisional; repair overwrites flagged rows) ----
    {
        float* out_som = out + (size_t)BATCH * (K1 + LAT);
        for (int idx = t; idx < BM * LAT; idx += NTHR) {
            int rr = idx >> 5, l = idx & (LAT - 1);
            out_som[(row0 + rr) * LAT + l] = prS[winS[rr] * LAT + l];
        }
        const float4* tab = (const float4*)g_recon_table4;
        float4* outr = (float4*)out;
        for (int idx = t; idx < BM * (K1 / 4); idx += NTHR) {
            int rr = idx / (K1 / 4);
            int q  = idx - rr * (K1 / 4);
            outr[(row0 + rr) * (K1 / 4) + q] = tab[winS[rr] * (K1 / 4) + q];
        }
    }
}

// ---------------- repair kernel: exact fp32 path (R3/R4 order) ----------------
#define RROWS 8
__global__ void __launch_bounds__(256)
repair_kernel(const float* __restrict__ x,
              const float* __restrict__ We1,
              const float* __restrict__ be1,
              const float* __restrict__ We2,
              const float* __restrict__ be2,
              const float* __restrict__ proto,
              float* __restrict__ out) {
    __shared__ float xr[RROWS][K1];
    __shared__ float h8[RROWS][HSTRIDE];
    __shared__ float z8[RROWS][LAT];
    __shared__ float pp[32];
    __shared__ float dd[RROWS * 32];
    __shared__ int   rows[RROWS];
    __shared__ int   win8[RROWS];
    const int t = threadIdx.x;
    int cnt = g_repair_count;
    if (cnt > BATCH) cnt = BATCH;

    for (int g = blockIdx.x; g * RROWS < cnt; g += gridDim.x) {
        const int nr = min(RROWS, cnt - g * RROWS);
        if (t < nr) rows[t] = g_repair_rows[g * RROWS + t];
        __syncthreads();
        for (int i = t; i < nr * K1; i += 256) {
            int rr = i / K1, k = i - rr * K1;
            xr[rr][k] = x[(size_t)rows[rr] * K1 + k];
        }
        __syncthreads();
        {
            float acc[RROWS];
#pragma unroll
            for (int rr = 0; rr < RROWS; rr++) acc[rr] = 0.0f;
#pragma unroll 4
            for (int k = 0; k < K1; k++) {
                float wv = We1[k * HID + t];
#pragma unroll
                for (int rr = 0; rr < RROWS; rr++)
                    acc[rr] = fmaf(xr[rr][k], wv, acc[rr]);
            }
            float b = be1[t];
#pragma unroll
            for (int rr = 0; rr < RROWS; rr++)
                h8[rr][t] = fmaxf(acc[rr] + b, 0.0f);
        }
        __syncthreads();
        if (t < nr * LAT) {
            int rr = t >> 5, l = t & 31;
            float a = 0.0f;
#pragma unroll 8
            for (int n = 0; n < HID; n++) a = fmaf(h8[rr][n], We2[n * LAT + l], a);
            a += be2[l];
            z8[rr][l] = a;
            out[(size_t)BATCH * K1 + (size_t)rows[rr] * LAT + l] = a;
        }
        if (t >= 224 && t < 224 + NPROTO) {
            int j = t - 224;
            const float* pj = proto + j * LAT;
            float a[32];
#pragma unroll
            for (int l = 0; l < 32; l++) a[l] = pj[l] * pj[l];
#pragma unroll
            for (int off = 16; off >= 1; off >>= 1)
#pragma unroll
                for (int i = 0; i < 16; i++)
                    if (i < off) a[i] += a[i + off];
            pp[j] = a[0];
        }
        __syncthreads();
        if (t < nr * NPROTO) {
            int rr = t / NPROTO, j = t - rr * NPROTO;
            const float* zr = z8[rr];
            const float* pj = proto + j * LAT;
            float zz = 0.0f, dot = 0.0f;
#pragma unroll
            for (int l = 0; l < LAT; l++) zz = fmaf(zr[l], zr[l], zz);
#pragma unroll
            for (int l = 0; l < LAT; l++) dot = fmaf(zr[l], pj[l], dot);
            dd[rr * 32 + j] = (zz - 2.0f * dot) + pp[j];
        }
        __syncthreads();
        if (t < nr) {
            const float* dr = dd + t * 32;
            float best = dr[0];
            int bi = 0;
#pragma unroll
            for (int j = 1; j < NPROTO; j++) {
                float v = dr[j];
                if (v < best) { best = v; bi = j; }
            }
            win8[t] = bi;
        }
        __syncthreads();
        for (int i = t; i < nr * LAT; i += 256) {
            int rr = i >> 5, l = i & 31;
            out[(size_t)BATCH * (K1 + LAT) + (size_t)rows[rr] * LAT + l] =
                proto[win8[rr] * LAT + l];
        }
        const float4* tab = (const float4*)g_recon_table4;
        float4* outr = (float4*)out;
        for (int i = t; i < nr * (K1 / 4); i += 256) {
            int rr = i / (K1 / 4), q = i - rr * (K1 / 4);
            outr[(size_t)rows[rr] * (K1 / 4) + q] = tab[win8[rr] * (K1 / 4) + q];
        }
        __syncthreads();
    }
}

extern "C" void kernel_launch(void* const* d_in, const int* in_sizes, int n_in,
                              void* d_out, int out_size) {
    const float* x    = (const float*)d_in[0];
    const float* We1  = (const float*)d_in[1];
    const float* be1  = (const float*)d_in[2];
    const float* We2  = (const float*)d_in[3];
    const float* be2  = (const float*)d_in[4];
    const float* Wd1  = (const float*)d_in[5];
    const float* bd1  = (const float*)d_in[6];
    const float* Wd2  = (const float*)d_in[7];
    const float* bd2  = (const float*)d_in[8];
    const float* prot = (const float*)d_in[9];
    float* out = (float*)d_out;

    zero_flags_kernel<<<1, 1>>>();
    prep_w_kernel<<<NCH, 256>>>(We1);
    decoder_table_kernel<<<NPROTO, 256>>>(Wd1, bd1, Wd2, bd2, prot);

    cudaFuncSetAttribute(dpsom_main_kernel,
                         cudaFuncAttributeMaxDynamicSharedMemorySize, SMEM_BYTES);
    dpsom_main_kernel<<<BATCH / BM, NTHR, SMEM_BYTES>>>(x, be1, We2, be2, prot, out);

    repair_kernel<<<256, 256>>>(x, We1, be1, We2, be2, prot, out);
}

// round 9
// speedup vs baseline: 1.2539x; 1.2539x over previous
#include <cuda_runtime.h>
#include <cuda_bf16.h>

// ---------------------------------------------------------------------------
// DPSOM, round 9.  vs R8 (652us: main 461us @ occ 12.5%, prep tail 191us):
//  * GEMM kernel: 2048 CTAs (64 rows x 128 cols), 256 thr, warp tile 32x32
//    (R6-proven lane maps), 97KB smem, ~100 regs -> 2 CTAs/SM (16 warps,
//    two independent barrier domains).  GEMM2 = per-CTA partial + fp32
//    atomicAdd into z (2 commutative contributions = deterministic).
//  * SOM/argmin/x_recon gather = separate memory-bound kernel.
//  * prep_w coalesced + register-swizzle; decoder_table split 4x.
//  * guard (5e-4) + exact-fp32 repair kernel unchanged.
//   output layout: [x_recon (B*784) | z (B*32) | som_z (B*32)]  (fp32)
// ---------------------------------------------------------------------------

#define BATCH   65536
#define K1      784
#define HID     256
#define LAT     32
#define NPROTO  25
#define BMR     64            // rows per CTA
#define BN      128           // cols per CTA
#define NTHR    256
#define NCH     13            // 13 x 64 k-chunks (832, tail zero-padded)
#define GUARD   5e-4f

// gemm smem: [0..512) be1-half; stages at 1024 + st*49152:
//   A_hi 8KB | A_lo 8KB | B_hi 16KB | B_lo 16KB
#define STG_BYTES  49152
#define SMEM_BYTES (1024 + 2 * STG_BYTES)   // 99328
// epilogue aliases stages: hS (64x132 f32) at float 256, we2s after.
#define HS_OFF  256
#define HSTR    132
#define WE2_OFF (HS_OFF + BMR * HSTR)       // 8704

typedef unsigned long long u64;
typedef unsigned int u32;

__device__ uint4  g_Bhi[NCH * 2048];   // [c][n(256) rows of 8 x uint4]
__device__ uint4  g_Blo[NCH * 2048];
__device__ float4 g_recon_table4[NPROTO * (K1 / 4)];
__device__ int    g_repair_count;
__device__ int    g_repair_rows[BATCH];

__host__ __device__ __forceinline__ u32 swz(u32 b) { return b ^ ((b >> 3) & 0x70); }

__device__ __forceinline__ u32 su(const void* p) {
    u32 a;
    asm("{ .reg .u64 t; cvta.to.shared.u64 t, %1; cvt.u32.u64 %0, t; }" : "=r"(a) : "l"(p));
    return a;
}
__device__ __forceinline__ void ldsm4(u32 a, u32& r0, u32& r1, u32& r2, u32& r3) {
    asm volatile("ldmatrix.sync.aligned.m8n8.x4.shared.b16 {%0,%1,%2,%3}, [%4];"
                 : "=r"(r0), "=r"(r1), "=r"(r2), "=r"(r3) : "r"(a));
}
__device__ __forceinline__ void mma16816(float* c, const u32* a, u32 b0, u32 b1) {
    asm volatile("mma.sync.aligned.m16n8k16.row.col.f32.bf16.bf16.f32 "
                 "{%0,%1,%2,%3},{%4,%5,%6,%7},{%8,%9},{%0,%1,%2,%3};"
                 : "+f"(c[0]), "+f"(c[1]), "+f"(c[2]), "+f"(c[3])
                 : "r"(a[0]), "r"(a[1]), "r"(a[2]), "r"(a[3]), "r"(b0), "r"(b1));
}
__device__ __forceinline__ void cpasync16(u32 dst, const void* src) {
    asm volatile("cp.async.cg.shared.global [%0], [%1], 16;" :: "r"(dst), "l"(src));
}
#define CP_COMMIT() asm volatile("cp.async.commit_group;")
#define CP_WAIT0()  asm volatile("cp.async.wait_group 0;")

// ---------------- prep kernels ----------------
__global__ void zero_z_kernel(float* __restrict__ out) {
    float4* z4 = (float4*)(out + (size_t)BATCH * K1);
    int i = blockIdx.x * 256 + threadIdx.x;           // 2048 blocks: 524288 f4
    z4[i] = make_float4(0.f, 0.f, 0.f, 0.f);
    if (blockIdx.x == 0 && threadIdx.x == 0) g_repair_count = 0;
}

// coalesced reads; per-thread row swizzle via 16B-unit permutation j^=(n&7)
__global__ void prep_w_kernel(const float* __restrict__ We1) {
    const int c = blockIdx.x;       // 13
    const int n = threadIdx.x;      // 256
    u32 hw[32], lw[32];
#pragma unroll 4
    for (int kp = 0; kp < 64; kp += 2) {
        int k0 = c * 64 + kp;
        float v0 = (k0 < K1)     ? We1[(size_t)k0 * HID + n] : 0.0f;
        float v1 = (k0 + 1 < K1) ? We1[(size_t)(k0 + 1) * HID + n] : 0.0f;
        __nv_bfloat16 h0 = __float2bfloat16(v0), h1 = __float2bfloat16(v1);
        __nv_bfloat16 l0 = __float2bfloat16(v0 - __bfloat162float(h0));
        __nv_bfloat16 l1 = __float2bfloat16(v1 - __bfloat162float(h1));
        hw[kp >> 1] = (u32)__bfloat16_as_ushort(h0) | ((u32)__bfloat16_as_ushort(h1) << 16);
        lw[kp >> 1] = (u32)__bfloat16_as_ushort(l0) | ((u32)__bfloat16_as_ushort(l1) << 16);
    }
#pragma unroll
    for (int j = 0; j < 8; j++) {
        int jd = j ^ (n & 7);
        uint4 h4 = make_uint4(hw[j*4], hw[j*4+1], hw[j*4+2], hw[j*4+3]);
        uint4 l4 = make_uint4(lw[j*4], lw[j*4+1], lw[j*4+2], lw[j*4+3]);
        g_Bhi[c * 2048 + n * 8 + jd] = h4;
        g_Blo[c * 2048 + n * 8 + jd] = l4;
    }
}

__global__ void decoder_table_kernel(const float* __restrict__ Wd1,
                                     const float* __restrict__ bd1,
                                     const float* __restrict__ Wd2,
                                     const float* __restrict__ bd2,
                                     const float* __restrict__ proto) {
    __shared__ float p[LAT];
    __shared__ float hd[HID];
    const int pid = blockIdx.x;
    const int t = threadIdx.x;
    if (t < LAT) p[t] = proto[pid * LAT + t];
    __syncthreads();
    if (t < HID) {
        float acc = 0.0f;
#pragma unroll
        for (int l = 0; l < LAT; l++) acc = fmaf(p[l], Wd1[l * HID + t], acc);
        hd[t] = fmaxf(acc + bd1[t], 0.0f);
    }
    __syncthreads();
    float* gt = (float*)g_recon_table4;
    int o = blockIdx.y * 196 + t;
    if (t < 196) {
        float acc = 0.0f;
#pragma unroll 8
        for (int n = 0; n < HID; n++) acc = fmaf(hd[n], Wd2[n * K1 + o], acc);
        float v = acc + bd2[o];
        gt[pid * K1 + o] = 1.0f / (1.0f + expf(-v));
    }
}

// ---------------- GEMM kernel (encoder) ----------------
__global__ void __launch_bounds__(NTHR, 2)
dpsom_gemm_kernel(const float* __restrict__ x,
                  const float* __restrict__ be1,
                  const float* __restrict__ We2,
                  const float* __restrict__ be2,
                  float* __restrict__ out) {
    extern __shared__ float sm[];
    const u32 sb = su(sm);
    const int t = threadIdx.x, lane = t & 31, w = t >> 5;
    const int wr = w >> 2, wc = w & 3;               // warp grid 2 x 4
    const int rowblk = blockIdx.x >> 1, nh = blockIdx.x & 1;
    const size_t row0 = (size_t)rowblk * BMR;
    const int ncol0 = nh * BN;

    const int ar = t >> 2, aq = t & 3;               // A loader: row, k-quarter
    const u32 bn  = (u32)((lane & 7) + ((lane & 16) ? 8 : 0));
    const u32 bkb = (u32)(((lane >> 3) & 1) * 16);

    if (t < BN) sm[t] = be1[ncol0 + t];              // be1 half, floats [0..128)

    float4 va[4];
    auto loadA = [&](int c) {
        const float4* xp = (const float4*)(x + (row0 + ar) * K1 + c * 64 + aq * 16);
#pragma unroll
        for (int j = 0; j < 4; j++) {
            int kk = c * 64 + aq * 16 + j * 4;
            va[j] = (kk < K1) ? xp[j] : make_float4(0.f, 0.f, 0.f, 0.f);
        }
    };
    auto storeA = [&](int st) {
        char* Sb = (char*)sm + 1024 + st * STG_BYTES;
#pragma unroll
        for (int j = 0; j < 4; j++) {
            float4 v = va[j];
            __nv_bfloat16 hx = __float2bfloat16(v.x), hy = __float2bfloat16(v.y);
            __nv_bfloat16 hz = __float2bfloat16(v.z), hw = __float2bfloat16(v.w);
            __nv_bfloat16 lx = __float2bfloat16(v.x - __bfloat162float(hx));
            __nv_bfloat16 ly = __float2bfloat16(v.y - __bfloat162float(hy));
            __nv_bfloat16 lz = __float2bfloat16(v.z - __bfloat162float(hz));
            __nv_bfloat16 lw = __float2bfloat16(v.w - __bfloat162float(hw));
            uint2 hv, lv;
            hv.x = (u32)__bfloat16_as_ushort(hx) | ((u32)__bfloat16_as_ushort(hy) << 16);
            hv.y = (u32)__bfloat16_as_ushort(hz) | ((u32)__bfloat16_as_ushort(hw) << 16);
            lv.x = (u32)__bfloat16_as_ushort(lx) | ((u32)__bfloat16_as_ushort(ly) << 16);
            lv.y = (u32)__bfloat16_as_ushort(lz) | ((u32)__bfloat16_as_ushort(lw) << 16);
            u32 o = swz((u32)ar * 128u + (u32)((aq * 16 + j * 4) * 2));
            *(uint2*)(Sb + o)        = hv;
            *(uint2*)(Sb + 8192 + o) = lv;
        }
    };
    auto loadB = [&](int c, int st) {
        const uint4* gh = g_Bhi + c * 2048 + nh * 1024;
        const uint4* gl = g_Blo + c * 2048 + nh * 1024;
        u32 dh = sb + 1024 + st * STG_BYTES + 16384;
        u32 dl = dh + 16384;
#pragma unroll
        for (int j = 0; j < 4; j++) {
            int o = j * NTHR + t;
            cpasync16(dh + o * 16, gh + o);
            cpasync16(dl + o * 16, gl + o);
        }
        CP_COMMIT();
    };

    // prologue
    loadA(0); storeA(0); loadB(0, 0);
    CP_WAIT0();
    __syncthreads();

    float acc[2][4][4];
#pragma unroll
    for (int m = 0; m < 2; m++)
#pragma unroll
        for (int n = 0; n < 4; n++)
#pragma unroll
            for (int q = 0; q < 4; q++) acc[m][n][q] = 0.0f;

#pragma unroll 1
    for (int c = 0; c < NCH; c++) {
        const int st = c & 1;
        if (c + 1 < NCH) { loadB(c + 1, st ^ 1); loadA(c + 1); }

        const u32 SB  = sb + 1024 + st * STG_BYTES;
        const u32 Ahi = SB, Alo = SB + 8192, Bhi = SB + 16384, Blo = SB + 32768;
        const u32 arow = (u32)((wr * 32 + (lane & 15)) * 128) + ((u32)(lane >> 4) << 4);
#pragma unroll
        for (int ks = 0; ks < 4; ks++) {
            const u32 kb = (u32)ks * 32u;
            u32 ah[8], al[8];
#pragma unroll
            for (int m = 0; m < 2; m++) {
                u32 o = arow + (u32)m * 2048u + kb;
                ldsm4(Ahi + swz(o), ah[m*4+0], ah[m*4+1], ah[m*4+2], ah[m*4+3]);
                ldsm4(Alo + swz(o), al[m*4+0], al[m*4+1], al[m*4+2], al[m*4+3]);
            }
            u32 bh[8], bl[8];
#pragma unroll
            for (int pr = 0; pr < 2; pr++) {
                u32 o = (u32)((wc * 32 + pr * 16 + bn) * 128) + kb + bkb;
                ldsm4(Bhi + swz(o), bh[pr*4+0], bh[pr*4+1], bh[pr*4+2], bh[pr*4+3]);
                ldsm4(Blo + swz(o), bl[pr*4+0], bl[pr*4+1], bl[pr*4+2], bl[pr*4+3]);
            }
#pragma unroll
            for (int m = 0; m < 2; m++)
#pragma unroll
                for (int nt = 0; nt < 4; nt++) {
                    float* cc = acc[m][nt];
                    u32 b0 = bh[(nt >> 1) * 4 + (nt & 1) * 2];
                    u32 b1 = bh[(nt >> 1) * 4 + (nt & 1) * 2 + 1];
                    u32 c0 = bl[(nt >> 1) * 4 + (nt & 1) * 2];
                    u32 c1 = bl[(nt >> 1) * 4 + (nt & 1) * 2 + 1];
                    mma16816(cc, &ah[m * 4], b0, b1);
                    mma16816(cc, &ah[m * 4], c0, c1);
                    mma16816(cc, &al[m * 4], b0, b1);
                }
        }
        if (c + 1 < NCH) storeA(st ^ 1);
        CP_WAIT0();
        __syncthreads();
    }

    // ---- h = relu(acc + be1) -> hS (64 x 132); stage region is dead ----
    float* hS = sm + HS_OFF;
    {
        const int g = lane >> 2, tq = (lane & 3) * 2;
#pragma unroll
        for (int m = 0; m < 2; m++)
#pragma unroll
            for (int nt = 0; nt < 4; nt++) {
                int row = wr * 32 + m * 16 + g;
                int col = wc * 32 + nt * 8 + tq;
                float b0 = sm[col], b1 = sm[col + 1];
                float* cc = acc[m][nt];
                hS[row * HSTR + col]           = fmaxf(cc[0] + b0, 0.0f);
                hS[row * HSTR + col + 1]       = fmaxf(cc[1] + b1, 0.0f);
                hS[(row + 8) * HSTR + col]     = fmaxf(cc[2] + b0, 0.0f);
                hS[(row + 8) * HSTR + col + 1] = fmaxf(cc[3] + b1, 0.0f);
            }
    }
    float* we2s = sm + WE2_OFF;           // this CTA's 128 x 32 slice of We2
    for (int i = t; i < BN * LAT; i += NTHR) we2s[i] = We2[ncol0 * LAT + i];
    __syncthreads();

    // ---- partial GEMM2: z += h_half . We2_half  (fp32 ffma2) ----
    {
        const int r = t >> 2;
        const int latb = (t & 3) * 8;
        u64 a0 = 0, a1 = 0, a2 = 0, a3 = 0;
        const float* hr = hS + r * HSTR;
        const float* wbase = we2s + latb;
#pragma unroll 8
        for (int n = 0; n < BN; n++) {
            float hv = hr[n];
            u64 hd;
            asm("mov.b64 %0,{%1,%1};" : "=l"(hd) : "f"(hv));
            ulonglong2 w0 = *(const ulonglong2*)(wbase + n * LAT);
            ulonglong2 w1 = *(const ulonglong2*)(wbase + n * LAT + 4);
            asm("fma.rn.f32x2 %0, %1, %2, %0;" : "+l"(a0) : "l"(hd), "l"(w0.x));
            asm("fma.rn.f32x2 %0, %1, %2, %0;" : "+l"(a1) : "l"(hd), "l"(w0.y));
            asm("fma.rn.f32x2 %0, %1, %2, %0;" : "+l"(a2) : "l"(hd), "l"(w1.x));
            asm("fma.rn.f32x2 %0, %1, %2, %0;" : "+l"(a3) : "l"(hd), "l"(w1.y));
        }
        float z[8];
        asm("mov.b64 {%0,%1},%2;" : "=f"(z[0]), "=f"(z[1]) : "l"(a0));
        asm("mov.b64 {%0,%1},%2;" : "=f"(z[2]), "=f"(z[3]) : "l"(a1));
        asm("mov.b64 {%0,%1},%2;" : "=f"(z[4]), "=f"(z[5]) : "l"(a2));
        asm("mov.b64 {%0,%1},%2;" : "=f"(z[6]), "=f"(z[7]) : "l"(a3));
        if (nh == 0) {
            float bz[8];
            *(float4*)bz       = *(const float4*)(be2 + latb);
            *(float4*)(bz + 4) = *(const float4*)(be2 + latb + 4);
#pragma unroll
            for (int j = 0; j < 8; j++) z[j] += bz[j];
        }
        float* zp = out + (size_t)BATCH * K1 + (row0 + r) * LAT + latb;
#pragma unroll
        for (int j = 0; j < 8; j++) atomicAdd(zp + j, z[j]);
    }
}

// ---------------- SOM + gather kernel ----------------
#define SROWS 256
__global__ void __launch_bounds__(256)
som_kernel(const float* __restrict__ proto, float* __restrict__ out) {
    __shared__ float zs[SROWS][33];
    __shared__ float proto_s[NPROTO * LAT];
    __shared__ float pn[32];
    __shared__ int   win[SROWS];
    const int t = threadIdx.x;
    const size_t row0 = (size_t)blockIdx.x * SROWS;
    const float* zg = out + (size_t)BATCH * K1;

    for (int i = t; i < NPROTO * LAT; i += 256) proto_s[i] = proto[i];
    // load z tile
    {
        const float4* z4 = (const float4*)(zg + row0 * LAT);
        for (int idx = t; idx < SROWS * 8; idx += 256) {
            int rr = idx >> 3, q = idx & 7;
            float4 v = z4[idx];
            zs[rr][q * 4]     = v.x;
            zs[rr][q * 4 + 1] = v.y;
            zs[rr][q * 4 + 2] = v.z;
            zs[rr][q * 4 + 3] = v.w;
        }
    }
    __syncthreads();
    if (t < NPROTO) {
        const float* pj = proto_s + t * LAT;
        float a[32];
#pragma unroll
        for (int l = 0; l < 32; l++) a[l] = pj[l] * pj[l];
#pragma unroll
        for (int off = 16; off >= 1; off >>= 1)
#pragma unroll
            for (int i = 0; i < 16; i++)
                if (i < off) a[i] += a[i + off];
        pn[t] = a[0];
    }
    __syncthreads();
    // per-row: zz, 25 dists (reference form), argmin + guard
    {
        const float* zr = zs[t];
        float zz = 0.0f;
#pragma unroll
        for (int l = 0; l < LAT; l++) zz = fmaf(zr[l], zr[l], zz);
        float best = 3.4e38f, sec = 3.4e38f;
        int bi = 0;
#pragma unroll 1
        for (int j = 0; j < NPROTO; j++) {
            const float* pj = proto_s + j * LAT;
            float dot = 0.0f;
#pragma unroll
            for (int l = 0; l < LAT; l++) dot = fmaf(zr[l], pj[l], dot);
            float d = (zz - 2.0f * dot) + pn[j];
            if (d < best) { sec = best; best = d; bi = j; }
            else if (d < sec) sec = d;
        }
        win[t] = bi;
        if (sec - best < GUARD) {
            int idx = atomicAdd(&g_repair_count, 1);
            if (idx < BATCH) g_repair_rows[idx] = (int)(row0 + t);
        }
    }
    __syncthreads();
    // som_z
    {
        float* out_som = out + (size_t)BATCH * (K1 + LAT);
        for (int idx = t; idx < SROWS * LAT; idx += 256) {
            int rr = idx >> 5, l = idx & 31;
            out_som[(row0 + rr) * LAT + l] = proto_s[win[rr] * LAT + l];
        }
    }
    // x_recon gather
    {
        const float4* tab = (const float4*)g_recon_table4;
        float4* outr = (float4*)out;
        for (int idx = t; idx < SROWS * (K1 / 4); idx += 256) {
            int rr = idx / (K1 / 4), q = idx - rr * (K1 / 4);
            outr[(row0 + rr) * (K1 / 4) + q] = tab[win[rr] * (K1 / 4) + q];
        }
    }
}

// ---------------- repair kernel: exact fp32 path (R3/R4 order) ----------------
#define RROWS 8
__global__ void __launch_bounds__(256)
repair_kernel(const float* __restrict__ x,
              const float* __restrict__ We1,
              const float* __restrict__ be1,
              const float* __restrict__ We2,
              const float* __restrict__ be2,
              const float* __restrict__ proto,
              float* __restrict__ out) {
    __shared__ float xr[RROWS][K1];
    __shared__ float h8[RROWS][HID + 1];
    __shared__ float z8[RROWS][LAT];
    __shared__ float pp[32];
    __shared__ float dd[RROWS * 32];
    __shared__ int   rows[RROWS];
    __shared__ int   win8[RROWS];
    const int t = threadIdx.x;
    int cnt = g_repair_count;
    if (cnt > BATCH) cnt = BATCH;

    for (int g = blockIdx.x; g * RROWS < cnt; g += gridDim.x) {
        const int nr = min(RROWS, cnt - g * RROWS);
        if (t < nr) rows[t] = g_repair_rows[g * RROWS + t];
        __syncthreads();
        for (int i = t; i < nr * K1; i += 256) {
            int rr = i / K1, k = i - rr * K1;
            xr[rr][k] = x[(size_t)rows[rr] * K1 + k];
        }
        __syncthreads();
        {
            float acc[RROWS];
#pragma unroll
            for (int rr = 0; rr < RROWS; rr++) acc[rr] = 0.0f;
#pragma unroll 4
            for (int k = 0; k < K1; k++) {
                float wv = We1[k * HID + t];
#pragma unroll
                for (int rr = 0; rr < RROWS; rr++)
                    acc[rr] = fmaf(xr[rr][k], wv, acc[rr]);
            }
            float b = be1[t];
#pragma unroll
            for (int rr = 0; rr < RROWS; rr++)
                h8[rr][t] = fmaxf(acc[rr] + b, 0.0f);
        }
        __syncthreads();
        if (t < nr * LAT) {
            int rr = t >> 5, l = t & 31;
            float a = 0.0f;
#pragma unroll 8
            for (int n = 0; n < HID; n++) a = fmaf(h8[rr][n], We2[n * LAT + l], a);
            a += be2[l];
            z8[rr][l] = a;
            out[(size_t)BATCH * K1 + (size_t)rows[rr] * LAT + l] = a;
        }
        if (t >= 224 && t < 224 + NPROTO) {
            int j = t - 224;
            const float* pj = proto + j * LAT;
            float a[32];
#pragma unroll
            for (int l = 0; l < 32; l++) a[l] = pj[l] * pj[l];
#pragma unroll
            for (int off = 16; off >= 1; off >>= 1)
#pragma unroll
                for (int i = 0; i < 16; i++)
                    if (i < off) a[i] += a[i + off];
            pp[j] = a[0];
        }
        __syncthreads();
        if (t < nr * NPROTO) {
            int rr = t / NPROTO, j = t - rr * NPROTO;
            const float* zr = z8[rr];
            const float* pj = proto + j * LAT;
            float zz = 0.0f, dot = 0.0f;
#pragma unroll
            for (int l = 0; l < LAT; l++) zz = fmaf(zr[l], zr[l], zz);
#pragma unroll
            for (int l = 0; l < LAT; l++) dot = fmaf(zr[l], pj[l], dot);
            dd[rr * 32 + j] = (zz - 2.0f * dot) + pp[j];
        }
        __syncthreads();
        if (t < nr) {
            const float* dr = dd + t * 32;
            float best = dr[0];
            int bi = 0;
#pragma unroll
            for (int j = 1; j < NPROTO; j++) {
                float v = dr[j];
                if (v < best) { best = v; bi = j; }
            }
            win8[t] = bi;
        }
        __syncthreads();
        for (int i = t; i < nr * LAT; i += 256) {
            int rr = i >> 5, l = i & 31;
            out[(size_t)BATCH * (K1 + LAT) + (size_t)rows[rr] * LAT + l] =
                proto[win8[rr] * LAT + l];
        }
        const float4* tab = (const float4*)g_recon_table4;
        float4* outr = (float4*)out;
        for (int i = t; i < nr * (K1 / 4); i += 256) {
            int rr = i / (K1 / 4), q = i - rr * (K1 / 4);
            outr[(size_t)rows[rr] * (K1 / 4) + q] = tab[win8[rr] * (K1 / 4) + q];
        }
        __syncthreads();
    }
}

extern "C" void kernel_launch(void* const* d_in, const int* in_sizes, int n_in,
                              void* d_out, int out_size) {
    const float* x    = (const float*)d_in[0];
    const float* We1  = (const float*)d_in[1];
    const float* be1  = (const float*)d_in[2];
    const float* We2  = (const float*)d_in[3];
    const float* be2  = (const float*)d_in[4];
    const float* Wd1  = (const float*)d_in[5];
    const float* bd1  = (const float*)d_in[6];
    const float* Wd2  = (const float*)d_in[7];
    const float* bd2  = (const float*)d_in[8];
    const float* prot = (const float*)d_in[9];
    float* out = (float*)d_out;

    zero_z_kernel<<<2048, 256>>>(out);
    prep_w_kernel<<<NCH, 256>>>(We1);
    decoder_table_kernel<<<dim3(NPROTO, 4), 256>>>(Wd1, bd1, Wd2, bd2, prot);

    cudaFuncSetAttribute(dpsom_gemm_kernel,
                         cudaFuncAttributeMaxDynamicSharedMemorySize, SMEM_BYTES);
    dpsom_gemm_kernel<<<(BATCH / BMR) * 2, NTHR, SMEM_BYTES>>>(x, be1, We2, be2, out);

    som_kernel<<<BATCH / SROWS, 256>>>(prot, out);
    repair_kernel<<<256, 256>>>(x, We1, be1, We2, be2, prot, out);
}

// round 10
// speedup vs baseline: 1.4268x; 1.1379x over previous
#include <cuda_runtime.h>
#include <cuda_fp16.h>

// ---------------------------------------------------------------------------
// DPSOM, round 10.  vs R9 (520us: GEMM 315us tensor 43.7%, som tail ~150us):
//  * 2-term fp16 split: x_hi*W_hi + x_hi*W_lo (x_lo dropped, |err| ~1e-4 on z;
//    tensor floor 138us -> 92us, A operand halves: only fp16(x) needed).
//  * One fused kernel: CTA = 64 rows x 256 cols (full HID) -> z completes
//    in-CTA (no atomics), som/argmin/x_recon gather in the CTA epilogue so
//    the 180MB output write overlaps other CTAs' GEMM across 3.5 waves.
//  * warp tile 64x32 (8 warps, 1x8 grid): B fragments single-consumer.
//  * 26 virtual chunks (13 k-chunks x {W_hi,W_lo}), B double-buffered 32KB,
//    A (8KB) reused for the hi/lo pair.
//  * GUARD 1e-2 (>=2x worst-case dist-gap error), exact-fp32 repair kernel.
//   output layout: [x_recon (B*784) | z (B*32) | som_z (B*32)]  (fp32)
// ---------------------------------------------------------------------------

#define BATCH   65536
#define K1      784
#define HID     256
#define LAT     32
#define NPROTO  25
#define BMR     64
#define NTHR    256
#define NCH     13
#define VCH     26
#define GUARD   1e-2f

// smem bytes: [0..1024) be1; A stages 8KB @1024,9216; B stages 32KB @17408,50176
// epilogue (floats, aliases stages): hS@256 (64x257), we2@16704, zs@24896 (64x33),
// proto@27008, pn@27808, win@27840
#define ASTG(i) (1024 + (i) * 8192)
#define BSTG(i) (17408 + (i) * 32768)
#define HS_OFF   256
#define HSTR     257
#define WE2_OFF  16704
#define ZS_OFF   24896
#define ZSTR     33
#define PR_OFF   27008
#define PN_OFF   27808
#define WIN_OFF  27840
#define SMEM_FLOATS 27904
#define SMEM_BYTES  (SMEM_FLOATS * 4)   // 111616

typedef unsigned long long u64;
typedef unsigned int u32;

__device__ uint4  g_Bhi[NCH * 2048];   // fp16 W_hi, [c][n*8 + swizzled-j]
__device__ uint4  g_Blo[NCH * 2048];   // fp16 W_lo
__device__ float4 g_recon_table4[NPROTO * (K1 / 4)];
__device__ int    g_repair_count;
__device__ int    g_repair_rows[BATCH];

__host__ __device__ __forceinline__ u32 swz(u32 b) { return b ^ ((b >> 3) & 0x70); }

__device__ __forceinline__ u32 su(const void* p) {
    u32 a;
    asm("{ .reg .u64 t; cvta.to.shared.u64 t, %1; cvt.u32.u64 %0, t; }" : "=r"(a) : "l"(p));
    return a;
}
__device__ __forceinline__ void ldsm4(u32 a, u32& r0, u32& r1, u32& r2, u32& r3) {
    asm volatile("ldmatrix.sync.aligned.m8n8.x4.shared.b16 {%0,%1,%2,%3}, [%4];"
                 : "=r"(r0), "=r"(r1), "=r"(r2), "=r"(r3) : "r"(a));
}
__device__ __forceinline__ void mma16816h(float* c, const u32* a, u32 b0, u32 b1) {
    asm volatile("mma.sync.aligned.m16n8k16.row.col.f32.f16.f16.f32 "
                 "{%0,%1,%2,%3},{%4,%5,%6,%7},{%8,%9},{%0,%1,%2,%3};"
                 : "+f"(c[0]), "+f"(c[1]), "+f"(c[2]), "+f"(c[3])
                 : "r"(a[0]), "r"(a[1]), "r"(a[2]), "r"(a[3]), "r"(b0), "r"(b1));
}
__device__ __forceinline__ void cpasync16(u32 dst, const void* src) {
    asm volatile("cp.async.cg.shared.global [%0], [%1], 16;" :: "r"(dst), "l"(src));
}
#define CP_COMMIT() asm volatile("cp.async.commit_group;")
#define CP_WAIT0()  asm volatile("cp.async.wait_group 0;")

__device__ __forceinline__ u32 pack2h(float a, float b) {
    __half ha = __float2half_rn(a), hb = __float2half_rn(b);
    return (u32)__half_as_ushort(ha) | ((u32)__half_as_ushort(hb) << 16);
}

// ---------------- prep kernels ----------------
__global__ void prep_w_kernel(const float* __restrict__ We1) {
    const int c = blockIdx.x;       // 13
    const int n = threadIdx.x;      // 256
    if (c == 0 && n == 0) g_repair_count = 0;
    u32 hw[32], lw[32];
#pragma unroll 4
    for (int kp = 0; kp < 64; kp += 2) {
        int k0 = c * 64 + kp;
        float v0 = (k0 < K1)     ? We1[(size_t)k0 * HID + n] : 0.0f;
        float v1 = (k0 + 1 < K1) ? We1[(size_t)(k0 + 1) * HID + n] : 0.0f;
        __half h0 = __float2half_rn(v0), h1 = __float2half_rn(v1);
        float l0f = v0 - __half2float(h0), l1f = v1 - __half2float(h1);
        __half l0 = __float2half_rn(l0f), l1 = __float2half_rn(l1f);
        hw[kp >> 1] = (u32)__half_as_ushort(h0) | ((u32)__half_as_ushort(h1) << 16);
        lw[kp >> 1] = (u32)__half_as_ushort(l0) | ((u32)__half_as_ushort(l1) << 16);
    }
#pragma unroll
    for (int j = 0; j < 8; j++) {
        int jd = j ^ (n & 7);      // implements 128B-row swizzle (R9-proven)
        g_Bhi[c * 2048 + n * 8 + jd] = make_uint4(hw[j*4], hw[j*4+1], hw[j*4+2], hw[j*4+3]);
        g_Blo[c * 2048 + n * 8 + jd] = make_uint4(lw[j*4], lw[j*4+1], lw[j*4+2], lw[j*4+3]);
    }
}

__global__ void decoder_table_kernel(const float* __restrict__ Wd1,
                                     const float* __restrict__ bd1,
                                     const float* __restrict__ Wd2,
                                     const float* __restrict__ bd2,
                                     const float* __restrict__ proto) {
    __shared__ float p[LAT];
    __shared__ float hd[HID];
    const int pid = blockIdx.x;
    const int t = threadIdx.x;
    if (t < LAT) p[t] = proto[pid * LAT + t];
    __syncthreads();
    if (t < HID) {
        float acc = 0.0f;
#pragma unroll
        for (int l = 0; l < LAT; l++) acc = fmaf(p[l], Wd1[l * HID + t], acc);
        hd[t] = fmaxf(acc + bd1[t], 0.0f);
    }
    __syncthreads();
    float* gt = (float*)g_recon_table4;
    int o = blockIdx.y * 196 + t;
    if (t < 196) {
        float acc = 0.0f;
#pragma unroll 8
        for (int n = 0; n < HID; n++) acc = fmaf(hd[n], Wd2[n * K1 + o], acc);
        float v = acc + bd2[o];
        gt[pid * K1 + o] = 1.0f / (1.0f + expf(-v));
    }
}

// ---------------- fused kernel ----------------
__global__ void __launch_bounds__(NTHR, 2)
dpsom_fused_kernel(const float* __restrict__ x,
                   const float* __restrict__ be1,
                   const float* __restrict__ We2,
                   const float* __restrict__ be2,
                   const float* __restrict__ proto,
                   float* __restrict__ out) {
    extern __shared__ float sm[];
    const u32 sb = su(sm);
    const int t = threadIdx.x, lane = t & 31, w = t >> 5;
    const int wn0 = w * 32;                       // warp col range (1x8 grid)
    const size_t row0 = (size_t)blockIdx.x * BMR;

    const int ar = t >> 2, aq = t & 3;            // A loader: row, k-quarter(16)
    const u32 bn  = (u32)((lane & 7) + ((lane & 16) ? 8 : 0));
    const u32 bkb = (u32)(((lane >> 3) & 1) * 16);

    sm[t] = be1[t];                               // floats [0..256)

    u32 va[8];   // fp16-packed A prefetch (8 k-pairs = 16 floats)
    auto loadA = [&](int ca) {
        const float4* xp = (const float4*)(x + (row0 + ar) * K1 + ca * 64 + aq * 16);
#pragma unroll
        for (int j = 0; j < 4; j++) {
            int kk = ca * 64 + aq * 16 + j * 4;
            float4 v = (kk < K1) ? xp[j] : make_float4(0.f, 0.f, 0.f, 0.f);
            va[j * 2]     = pack2h(v.x, v.y);
            va[j * 2 + 1] = pack2h(v.z, v.w);
        }
    };
    auto storeA = [&](int ca) {
        char* Sb = (char*)sm + ASTG(ca & 1);
#pragma unroll
        for (int j = 0; j < 4; j++) {
            u32 o = swz((u32)ar * 128u + (u32)((aq * 16 + j * 4) * 2));
            *(uint2*)(Sb + o) = make_uint2(va[j * 2], va[j * 2 + 1]);
        }
    };
    auto loadB = [&](int vc) {
        const uint4* src = ((vc & 1) ? g_Blo : g_Bhi) + (vc >> 1) * 2048;
        u32 dst = sb + BSTG(vc & 1);
#pragma unroll
        for (int j = 0; j < 8; j++) {
            int o = j * NTHR + t;
            cpasync16(dst + o * 16, src + o);
        }
        CP_COMMIT();
    };

    // prologue: chunk 0 A + vchunk 0 B (W_hi)
    loadA(0); storeA(0); loadB(0);
    CP_WAIT0();
    __syncthreads();

    float acc[4][4][4];
#pragma unroll
    for (int m = 0; m < 4; m++)
#pragma unroll
        for (int n = 0; n < 4; n++)
#pragma unroll
            for (int q = 0; q < 4; q++) acc[m][n][q] = 0.0f;

#pragma unroll 1
    for (int vc = 0; vc < VCH; vc++) {
        const bool pfB = (vc + 1 < VCH);
        const bool pfA = ((vc & 1) == 1) && ((vc >> 1) + 1 < NCH);
        if (pfB) loadB(vc + 1);
        if (pfA) loadA((vc >> 1) + 1);

        const u32 Ab = sb + ASTG((vc >> 1) & 1);
        const u32 Bb = sb + BSTG(vc & 1);
#pragma unroll
        for (int ks = 0; ks < 4; ks++) {
            const u32 kb = (u32)ks * 32u;
            u32 ah[16];
#pragma unroll
            for (int m = 0; m < 4; m++) {
                u32 o = (u32)((m * 16 + (lane & 15)) * 128) + ((u32)(lane >> 4) << 4) + kb;
                ldsm4(Ab + swz(o), ah[m*4+0], ah[m*4+1], ah[m*4+2], ah[m*4+3]);
            }
            u32 bb[8];
#pragma unroll
            for (int pr = 0; pr < 2; pr++) {
                u32 o = (u32)((wn0 + pr * 16 + bn) * 128) + kb + bkb;
                ldsm4(Bb + swz(o), bb[pr*4+0], bb[pr*4+1], bb[pr*4+2], bb[pr*4+3]);
            }
#pragma unroll
            for (int m = 0; m < 4; m++)
#pragma unroll
                for (int nt = 0; nt < 4; nt++)
                    mma16816h(acc[m][nt], &ah[m * 4],
                              bb[(nt >> 1) * 4 + (nt & 1) * 2],
                              bb[(nt >> 1) * 4 + (nt & 1) * 2 + 1]);
        }
        if (pfA) storeA((vc >> 1) + 1);
        if (pfB) CP_WAIT0();
        __syncthreads();
    }

    // ---- h = relu(acc + be1) -> hS (64 x 257); stages dead ----
    float* hS = sm + HS_OFF;
    {
        const int g = lane >> 2, tq = (lane & 3) * 2;
#pragma unroll
        for (int m = 0; m < 4; m++)
#pragma unroll
            for (int nt = 0; nt < 4; nt++) {
                int row = m * 16 + g;
                int col = wn0 + nt * 8 + tq;
                float b0 = sm[col], b1 = sm[col + 1];
                float* cc = acc[m][nt];
                hS[row * HSTR + col]           = fmaxf(cc[0] + b0, 0.0f);
                hS[row * HSTR + col + 1]       = fmaxf(cc[1] + b1, 0.0f);
                hS[(row + 8) * HSTR + col]     = fmaxf(cc[2] + b0, 0.0f);
                hS[(row + 8) * HSTR + col + 1] = fmaxf(cc[3] + b1, 0.0f);
            }
    }
    float* we2s = sm + WE2_OFF;
    float* zsS  = sm + ZS_OFF;
    float* prS  = sm + PR_OFF;
    float* pnS  = sm + PN_OFF;
    int*   winS = (int*)(sm + WIN_OFF);
    for (int i = t; i < HID * LAT; i += NTHR) we2s[i] = We2[i];
    for (int i = t; i < NPROTO * LAT; i += NTHR) prS[i] = proto[i];
    __syncthreads();

    // ---- GEMM2 (fp32): thread -> (row r, 8 lat cols) ----
    {
        float* out_z = out + (size_t)BATCH * K1;
        const int r = t >> 2;
        const int latb = (t & 3) * 8;
        u64 a0 = 0, a1 = 0, a2 = 0, a3 = 0;
        const float* hr = hS + r * HSTR;
        const float* wbase = we2s + latb;
#pragma unroll 8
        for (int n = 0; n < HID; n++) {
            float hv = hr[n];
            u64 hd;
            asm("mov.b64 %0,{%1,%1};" : "=l"(hd) : "f"(hv));
            ulonglong2 w0 = *(const ulonglong2*)(wbase + n * LAT);
            ulonglong2 w1 = *(const ulonglong2*)(wbase + n * LAT + 4);
            asm("fma.rn.f32x2 %0, %1, %2, %0;" : "+l"(a0) : "l"(hd), "l"(w0.x));
            asm("fma.rn.f32x2 %0, %1, %2, %0;" : "+l"(a1) : "l"(hd), "l"(w0.y));
            asm("fma.rn.f32x2 %0, %1, %2, %0;" : "+l"(a2) : "l"(hd), "l"(w1.x));
            asm("fma.rn.f32x2 %0, %1, %2, %0;" : "+l"(a3) : "l"(hd), "l"(w1.y));
        }
        float z[8];
        asm("mov.b64 {%0,%1},%2;" : "=f"(z[0]), "=f"(z[1]) : "l"(a0));
        asm("mov.b64 {%0,%1},%2;" : "=f"(z[2]), "=f"(z[3]) : "l"(a1));
        asm("mov.b64 {%0,%1},%2;" : "=f"(z[4]), "=f"(z[5]) : "l"(a2));
        asm("mov.b64 {%0,%1},%2;" : "=f"(z[6]), "=f"(z[7]) : "l"(a3));
        float bz[8];
        *(float4*)bz       = *(const float4*)(be2 + latb);
        *(float4*)(bz + 4) = *(const float4*)(be2 + latb + 4);
#pragma unroll
        for (int j = 0; j < 8; j++) z[j] += bz[j];
#pragma unroll
        for (int j = 0; j < 8; j++) zsS[r * ZSTR + latb + j] = z[j];
        *(float4*)(out_z + (row0 + r) * LAT + latb)     = *(float4*)z;
        *(float4*)(out_z + (row0 + r) * LAT + latb + 4) = *(float4*)(z + 4);
    }
    __syncthreads();

    // ---- pn (shuffle-tree order) ----
    if (t < NPROTO) {
        const float* pj = prS + t * LAT;
        float a[32];
#pragma unroll
        for (int l = 0; l < 32; l++) a[l] = pj[l] * pj[l];
#pragma unroll
        for (int off = 16; off >= 1; off >>= 1)
#pragma unroll
            for (int i = 0; i < 16; i++)
                if (i < off) a[i] += a[i + off];
        pnS[t] = a[0];
    }
    __syncthreads();

    // ---- per-row argmin (reference form) + guard ----
    if (t < BMR) {
        const float* zr = zsS + t * ZSTR;
        float zz = 0.0f;
#pragma unroll
        for (int l = 0; l < LAT; l++) zz = fmaf(zr[l], zr[l], zz);
        float best = 3.4e38f, sec = 3.4e38f;
        int bi = 0;
#pragma unroll 1
        for (int j = 0; j < NPROTO; j++) {
            const float* pj = prS + j * LAT;
            float dot = 0.0f;
#pragma unroll
            for (int l = 0; l < LAT; l++) dot = fmaf(zr[l], pj[l], dot);
            float d = (zz - 2.0f * dot) + pnS[j];
            if (d < best) { sec = best; best = d; bi = j; }
            else if (d < sec) sec = d;
        }
        winS[t] = bi;
        if (sec - best < GUARD) {
            int idx = atomicAdd(&g_repair_count, 1);
            if (idx < BATCH) g_repair_rows[idx] = (int)(row0 + t);
        }
    }
    __syncthreads();

    // ---- som_z + x_recon (overlapped with other CTAs' GEMM) ----
    {
        float* out_som = out + (size_t)BATCH * (K1 + LAT);
        for (int idx = t; idx < BMR * LAT; idx += NTHR) {
            int rr = idx >> 5, l = idx & 31;
            out_som[(row0 + rr) * LAT + l] = prS[winS[rr] * LAT + l];
        }
        const float4* tab = (const float4*)g_recon_table4;
        float4* outr = (float4*)out;
        for (int idx = t; idx < BMR * (K1 / 4); idx += NTHR) {
            int rr = idx / (K1 / 4), q = idx - rr * (K1 / 4);
            outr[(row0 + rr) * (K1 / 4) + q] = tab[winS[rr] * (K1 / 4) + q];
        }
    }
}

// ---------------- repair kernel: exact fp32 path (R3/R4 order) ----------------
#define RROWS 8
__global__ void __launch_bounds__(256)
repair_kernel(const float* __restrict__ x,
              const float* __restrict__ We1,
              const float* __restrict__ be1,
              const float* __restrict__ We2,
              const float* __restrict__ be2,
              const float* __restrict__ proto,
              float* __restrict__ out) {
    __shared__ float xr[RROWS][K1];
    __shared__ float h8[RROWS][HID + 1];
    __shared__ float z8[RROWS][LAT];
    __shared__ float pp[32];
    __shared__ float dd[RROWS * 32];
    __shared__ int   rows[RROWS];
    __shared__ int   win8[RROWS];
    const int t = threadIdx.x;
    int cnt = g_repair_count;
    if (cnt > BATCH) cnt = BATCH;

    for (int g = blockIdx.x; g * RROWS < cnt; g += gridDim.x) {
        const int nr = min(RROWS, cnt - g * RROWS);
        if (t < nr) rows[t] = g_repair_rows[g * RROWS + t];
        __syncthreads();
        for (int i = t; i < nr * K1; i += 256) {
            int rr = i / K1, k = i - rr * K1;
            xr[rr][k] = x[(size_t)rows[rr] * K1 + k];
        }
        __syncthreads();
        {
            float acc[RROWS];
#pragma unroll
            for (int rr = 0; rr < RROWS; rr++) acc[rr] = 0.0f;
#pragma unroll 4
            for (int k = 0; k < K1; k++) {
                float wv = We1[k * HID + t];
#pragma unroll
                for (int rr = 0; rr < RROWS; rr++)
                    acc[rr] = fmaf(xr[rr][k], wv, acc[rr]);
            }
            float b = be1[t];
#pragma unroll
            for (int rr = 0; rr < RROWS; rr++)
                h8[rr][t] = fmaxf(acc[rr] + b, 0.0f);
        }
        __syncthreads();
        if (t < nr * LAT) {
            int rr = t >> 5, l = t & 31;
            float a = 0.0f;
#pragma unroll 8
            for (int n = 0; n < HID; n++) a = fmaf(h8[rr][n], We2[n * LAT + l], a);
            a += be2[l];
            z8[rr][l] = a;
            out[(size_t)BATCH * K1 + (size_t)rows[rr] * LAT + l] = a;
        }
        if (t >= 224 && t < 224 + NPROTO) {
            int j = t - 224;
            const float* pj = proto + j * LAT;
            float a[32];
#pragma unroll
            for (int l = 0; l < 32; l++) a[l] = pj[l] * pj[l];
#pragma unroll
            for (int off = 16; off >= 1; off >>= 1)
#pragma unroll
                for (int i = 0; i < 16; i++)
                    if (i < off) a[i] += a[i + off];
            pp[j] = a[0];
        }
        __syncthreads();
        if (t < nr * NPROTO) {
            int rr = t / NPROTO, j = t - rr * NPROTO;
            const float* zr = z8[rr];
            const float* pj = proto + j * LAT;
            float zz = 0.0f, dot = 0.0f;
#pragma unroll
            for (int l = 0; l < LAT; l++) zz = fmaf(zr[l], zr[l], zz);
#pragma unroll
            for (int l = 0; l < LAT; l++) dot = fmaf(zr[l], pj[l], dot);
            dd[rr * 32 + j] = (zz - 2.0f * dot) + pp[j];
        }
        __syncthreads();
        if (t < nr) {
            const float* dr = dd + t * 32;
            float best = dr[0];
            int bi = 0;
#pragma unroll
            for (int j = 1; j < NPROTO; j++) {
                float v = dr[j];
                if (v < best) { best = v; bi = j; }
            }
            win8[t] = bi;
        }
        __syncthreads();
        for (int i = t; i < nr * LAT; i += 256) {
            int rr = i >> 5, l = i & 31;
            out[(size_t)BATCH * (K1 + LAT) + (size_t)rows[rr] * LAT + l] =
                proto[win8[rr] * LAT + l];
        }
        const float4* tab = (const float4*)g_recon_table4;
        float4* outr = (float4*)out;
        for (int i = t; i < nr * (K1 / 4); i += 256) {
            int rr = i / (K1 / 4), q = i - rr * (K1 / 4);
            outr[(size_t)rows[rr] * (K1 / 4) + q] = tab[win8[rr] * (K1 / 4) + q];
        }
        __syncthreads();
    }
}

extern "C" void kernel_launch(void* const* d_in, const int* in_sizes, int n_in,
                              void* d_out, int out_size) {
    const float* x    = (const float*)d_in[0];
    const float* We1  = (const float*)d_in[1];
    const float* be1  = (const float*)d_in[2];
    const float* We2  = (const float*)d_in[3];
    const float* be2  = (const float*)d_in[4];
    const float* Wd1  = (const float*)d_in[5];
    const float* bd1  = (const float*)d_in[6];
    const float* Wd2  = (const float*)d_in[7];
    const float* bd2  = (const float*)d_in[8];
    const float* prot = (const float*)d_in[9];
    float* out = (float*)d_out;

    prep_w_kernel<<<NCH, 256>>>(We1);
    decoder_table_kernel<<<dim3(NPROTO, 4), 256>>>(Wd1, bd1, Wd2, bd2, prot);

    cudaFuncSetAttribute(dpsom_fused_kernel,
                         cudaFuncAttributeMaxDynamicSharedMemorySize, SMEM_BYTES);
    dpsom_fused_kernel<<<BATCH / BMR, NTHR, SMEM_BYTES>>>(x, be1, We2, be2, prot, out);

    repair_kernel<<<256, 256>>>(x, We1, be1, We2, be2, prot, out);
}

// round 11
// speedup vs baseline: 1.4767x; 1.0350x over previous
#include <cuda_runtime.h>
#include <cuda_fp16.h>

// ---------------------------------------------------------------------------
// DPSOM, round 11.  vs R10 (457us: fused ~300us L2-BW-bound on W restream,
// repair_kernel 140us latency-bound):
//  * B triple-buffered (3x32KB), prefetch distance 2 via cp.async.wait_group 1;
//    A single-staged (8KB) to fit 107.5KB stages -> keeps 2 CTAs/SM.
//  * repair kernel: grid 512, k-loop unroll 8 (MLP) -> ~4x faster wall.
//  * everything else (2-term fp16 split, fused epilogue, GUARD 1e-2) as R10.
//   output layout: [x_recon (B*784) | z (B*32) | som_z (B*32)]  (fp32)
// ---------------------------------------------------------------------------

#define BATCH   65536
#define K1      784
#define HID     256
#define LAT     32
#define NPROTO  25
#define BMR     64
#define NTHR    256
#define NCH     13
#define VCH     26
#define GUARD   1e-2f

// smem bytes: [0..1024) be1; A stage 8KB @1024; B stages 32KB @9216,41984,74752
// epilogue (floats, aliases stages): hS@256 (64x257), we2@16704, zs@24896 (64x33),
// proto@27008, pn@27808, win@27840
#define ABASE    1024
#define BBASE    9216
#define HS_OFF   256
#define HSTR     257
#define WE2_OFF  16704
#define ZS_OFF   24896
#define ZSTR     33
#define PR_OFF   27008
#define PN_OFF   27808
#define WIN_OFF  27840
#define SMEM_FLOATS 27904
#define SMEM_BYTES  (SMEM_FLOATS * 4)   // 111616 (stages end at 107520)

typedef unsigned long long u64;
typedef unsigned int u32;

__device__ uint4  g_Bhi[NCH * 2048];   // fp16 W_hi, [c][n*8 + swizzled-j]
__device__ uint4  g_Blo[NCH * 2048];   // fp16 W_lo
__device__ float4 g_recon_table4[NPROTO * (K1 / 4)];
__device__ int    g_repair_count;
__device__ int    g_repair_rows[BATCH];

__host__ __device__ __forceinline__ u32 swz(u32 b) { return b ^ ((b >> 3) & 0x70); }

__device__ __forceinline__ u32 su(const void* p) {
    u32 a;
    asm("{ .reg .u64 t; cvta.to.shared.u64 t, %1; cvt.u32.u64 %0, t; }" : "=r"(a) : "l"(p));
    return a;
}
__device__ __forceinline__ void ldsm4(u32 a, u32& r0, u32& r1, u32& r2, u32& r3) {
    asm volatile("ldmatrix.sync.aligned.m8n8.x4.shared.b16 {%0,%1,%2,%3}, [%4];"
                 : "=r"(r0), "=r"(r1), "=r"(r2), "=r"(r3) : "r"(a));
}
__device__ __forceinline__ void mma16816h(float* c, const u32* a, u32 b0, u32 b1) {
    asm volatile("mma.sync.aligned.m16n8k16.row.col.f32.f16.f16.f32 "
                 "{%0,%1,%2,%3},{%4,%5,%6,%7},{%8,%9},{%0,%1,%2,%3};"
                 : "+f"(c[0]), "+f"(c[1]), "+f"(c[2]), "+f"(c[3])
                 : "r"(a[0]), "r"(a[1]), "r"(a[2]), "r"(a[3]), "r"(b0), "r"(b1));
}
__device__ __forceinline__ void cpasync16(u32 dst, const void* src) {
    asm volatile("cp.async.cg.shared.global [%0], [%1], 16;" :: "r"(dst), "l"(src));
}
#define CP_COMMIT() asm volatile("cp.async.commit_group;")
#define CP_WAIT0()  asm volatile("cp.async.wait_group 0;")
#define CP_WAIT1()  asm volatile("cp.async.wait_group 1;")

__device__ __forceinline__ u32 pack2h(float a, float b) {
    __half ha = __float2half_rn(a), hb = __float2half_rn(b);
    return (u32)__half_as_ushort(ha) | ((u32)__half_as_ushort(hb) << 16);
}

// ---------------- prep kernels ----------------
__global__ void prep_w_kernel(const float* __restrict__ We1) {
    const int c = blockIdx.x;       // 13
    const int n = threadIdx.x;      // 256
    if (c == 0 && n == 0) g_repair_count = 0;
    u32 hw[32], lw[32];
#pragma unroll 4
    for (int kp = 0; kp < 64; kp += 2) {
        int k0 = c * 64 + kp;
        float v0 = (k0 < K1)     ? We1[(size_t)k0 * HID + n] : 0.0f;
        float v1 = (k0 + 1 < K1) ? We1[(size_t)(k0 + 1) * HID + n] : 0.0f;
        __half h0 = __float2half_rn(v0), h1 = __float2half_rn(v1);
        float l0f = v0 - __half2float(h0), l1f = v1 - __half2float(h1);
        __half l0 = __float2half_rn(l0f), l1 = __float2half_rn(l1f);
        hw[kp >> 1] = (u32)__half_as_ushort(h0) | ((u32)__half_as_ushort(h1) << 16);
        lw[kp >> 1] = (u32)__half_as_ushort(l0) | ((u32)__half_as_ushort(l1) << 16);
    }
#pragma unroll
    for (int j = 0; j < 8; j++) {
        int jd = j ^ (n & 7);      // 128B-row swizzle (R9/R10-proven)
        g_Bhi[c * 2048 + n * 8 + jd] = make_uint4(hw[j*4], hw[j*4+1], hw[j*4+2], hw[j*4+3]);
        g_Blo[c * 2048 + n * 8 + jd] = make_uint4(lw[j*4], lw[j*4+1], lw[j*4+2], lw[j*4+3]);
    }
}

__global__ void decoder_table_kernel(const float* __restrict__ Wd1,
                                     const float* __restrict__ bd1,
                                     const float* __restrict__ Wd2,
                                     const float* __restrict__ bd2,
                                     const float* __restrict__ proto) {
    __shared__ float p[LAT];
    __shared__ float hd[HID];
    const int pid = blockIdx.x;
    const int t = threadIdx.x;
    if (t < LAT) p[t] = proto[pid * LAT + t];
    __syncthreads();
    if (t < HID) {
        float acc = 0.0f;
#pragma unroll
        for (int l = 0; l < LAT; l++) acc = fmaf(p[l], Wd1[l * HID + t], acc);
        hd[t] = fmaxf(acc + bd1[t], 0.0f);
    }
    __syncthreads();
    float* gt = (float*)g_recon_table4;
    int o = blockIdx.y * 196 + t;
    if (t < 196) {
        float acc = 0.0f;
#pragma unroll 8
        for (int n = 0; n < HID; n++) acc = fmaf(hd[n], Wd2[n * K1 + o], acc);
        float v = acc + bd2[o];
        gt[pid * K1 + o] = 1.0f / (1.0f + expf(-v));
    }
}

// ---------------- fused kernel ----------------
__global__ void __launch_bounds__(NTHR, 2)
dpsom_fused_kernel(const float* __restrict__ x,
                   const float* __restrict__ be1,
                   const float* __restrict__ We2,
                   const float* __restrict__ be2,
                   const float* __restrict__ proto,
                   float* __restrict__ out) {
    extern __shared__ float sm[];
    const u32 sb = su(sm);
    const int t = threadIdx.x, lane = t & 31, w = t >> 5;
    const int wn0 = w * 32;                       // warp col slice (1x8 grid)
    const size_t row0 = (size_t)blockIdx.x * BMR;

    const int ar = t >> 2, aq = t & 3;            // A loader: row, k-quarter(16)
    const u32 bn  = (u32)((lane & 7) + ((lane & 16) ? 8 : 0));
    const u32 bkb = (u32)(((lane >> 3) & 1) * 16);

    sm[t] = be1[t];                               // floats [0..256)

    u32 va[8];
    auto loadA = [&](int ca) {
        const float4* xp = (const float4*)(x + (row0 + ar) * K1 + ca * 64 + aq * 16);
#pragma unroll
        for (int j = 0; j < 4; j++) {
            int kk = ca * 64 + aq * 16 + j * 4;
            float4 v = (kk < K1) ? xp[j] : make_float4(0.f, 0.f, 0.f, 0.f);
            va[j * 2]     = pack2h(v.x, v.y);
            va[j * 2 + 1] = pack2h(v.z, v.w);
        }
    };
    auto storeA = [&]() {
        char* Sb = (char*)sm + ABASE;
#pragma unroll
        for (int j = 0; j < 4; j++) {
            u32 o = swz((u32)ar * 128u + (u32)((aq * 16 + j * 4) * 2));
            *(uint2*)(Sb + o) = make_uint2(va[j * 2], va[j * 2 + 1]);
        }
    };
    auto loadB = [&](int vc) {
        const uint4* src = ((vc & 1) ? g_Blo : g_Bhi) + (vc >> 1) * 2048;
        u32 dst = sb + BBASE + (u32)(vc % 3) * 32768u;
#pragma unroll
        for (int j = 0; j < 8; j++) {
            int o = j * NTHR + t;
            cpasync16(dst + o * 16, src + o);
        }
        CP_COMMIT();
    };

    // prologue: A chunk 0 staged; B vc 0,1 in flight
    loadA(0); storeA(); loadB(0); loadB(1);
    CP_WAIT1();
    __syncthreads();

    float acc[4][4][4];
#pragma unroll
    for (int m = 0; m < 4; m++)
#pragma unroll
        for (int n = 0; n < 4; n++)
#pragma unroll
            for (int q = 0; q < 4; q++) acc[m][n][q] = 0.0f;

#pragma unroll 1
    for (int vc = 0; vc < VCH; vc++) {
        if (vc + 2 < VCH) loadB(vc + 2);
        const int c = vc >> 1;
        if (((vc & 1) == 0) && (c + 1 < NCH)) loadA(c + 1);

        const u32 Ab = sb + ABASE;
        const u32 Bb = sb + BBASE + (u32)(vc % 3) * 32768u;
#pragma unroll
        for (int ks = 0; ks < 4; ks++) {
            const u32 kb = (u32)ks * 32u;
            u32 ah[16];
#pragma unroll
            for (int m = 0; m < 4; m++) {
                u32 o = (u32)((m * 16 + (lane & 15)) * 128) + ((u32)(lane >> 4) << 4) + kb;
                ldsm4(Ab + swz(o), ah[m*4+0], ah[m*4+1], ah[m*4+2], ah[m*4+3]);
            }
            u32 bb[8];
#pragma unroll
            for (int pr = 0; pr < 2; pr++) {
                u32 o = (u32)((wn0 + pr * 16 + bn) * 128) + kb + bkb;
                ldsm4(Bb + swz(o), bb[pr*4+0], bb[pr*4+1], bb[pr*4+2], bb[pr*4+3]);
            }
#pragma unroll
            for (int m = 0; m < 4; m++)
#pragma unroll
                for (int nt = 0; nt < 4; nt++)
                    mma16816h(acc[m][nt], &ah[m * 4],
                              bb[(nt >> 1) * 4 + (nt & 1) * 2],
                              bb[(nt >> 1) * 4 + (nt & 1) * 2 + 1]);
        }
        // A single stage: refill after BOTH hi/lo vc of chunk c consumed it
        if (((vc & 1) == 1) && (c + 1 < NCH)) {
            __syncthreads();      // all warps done reading A stage
            storeA();
        }
        if (vc + 2 < VCH) CP_WAIT1(); else CP_WAIT0();
        __syncthreads();
    }

    // ---- h = relu(acc + be1) -> hS (64 x 257); stages dead ----
    float* hS = sm + HS_OFF;
    {
        const int g = lane >> 2, tq = (lane & 3) * 2;
#pragma unroll
        for (int m = 0; m < 4; m++)
#pragma unroll
            for (int nt = 0; nt < 4; nt++) {
                int row = m * 16 + g;
                int col = wn0 + nt * 8 + tq;
                float b0 = sm[col], b1 = sm[col + 1];
                float* cc = acc[m][nt];
                hS[row * HSTR + col]           = fmaxf(cc[0] + b0, 0.0f);
                hS[row * HSTR + col + 1]       = fmaxf(cc[1] + b1, 0.0f);
                hS[(row + 8) * HSTR + col]     = fmaxf(cc[2] + b0, 0.0f);
                hS[(row + 8) * HSTR + col + 1] = fmaxf(cc[3] + b1, 0.0f);
            }
    }
    float* we2s = sm + WE2_OFF;
    float* zsS  = sm + ZS_OFF;
    float* prS  = sm + PR_OFF;
    float* pnS  = sm + PN_OFF;
    int*   winS = (int*)(sm + WIN_OFF);
    for (int i = t; i < HID * LAT; i += NTHR) we2s[i] = We2[i];
    for (int i = t; i < NPROTO * LAT; i += NTHR) prS[i] = proto[i];
    __syncthreads();

    // ---- GEMM2 (fp32): thread -> (row r, 8 lat cols) ----
    {
        float* out_z = out + (size_t)BATCH * K1;
        const int r = t >> 2;
        const int latb = (t & 3) * 8;
        u64 a0 = 0, a1 = 0, a2 = 0, a3 = 0;
        const float* hr = hS + r * HSTR;
        const float* wbase = we2s + latb;
#pragma unroll 8
        for (int n = 0; n < HID; n++) {
            float hv = hr[n];
            u64 hd;
            asm("mov.b64 %0,{%1,%1};" : "=l"(hd) : "f"(hv));
            ulonglong2 w0 = *(const ulonglong2*)(wbase + n * LAT);
            ulonglong2 w1 = *(const ulonglong2*)(wbase + n * LAT + 4);
            asm("fma.rn.f32x2 %0, %1, %2, %0;" : "+l"(a0) : "l"(hd), "l"(w0.x));
            asm("fma.rn.f32x2 %0, %1, %2, %0;" : "+l"(a1) : "l"(hd), "l"(w0.y));
            asm("fma.rn.f32x2 %0, %1, %2, %0;" : "+l"(a2) : "l"(hd), "l"(w1.x));
            asm("fma.rn.f32x2 %0, %1, %2, %0;" : "+l"(a3) : "l"(hd), "l"(w1.y));
        }
        float z[8];
        asm("mov.b64 {%0,%1},%2;" : "=f"(z[0]), "=f"(z[1]) : "l"(a0));
        asm("mov.b64 {%0,%1},%2;" : "=f"(z[2]), "=f"(z[3]) : "l"(a1));
        asm("mov.b64 {%0,%1},%2;" : "=f"(z[4]), "=f"(z[5]) : "l"(a2));
        asm("mov.b64 {%0,%1},%2;" : "=f"(z[6]), "=f"(z[7]) : "l"(a3));
        float bz[8];
        *(float4*)bz       = *(const float4*)(be2 + latb);
        *(float4*)(bz + 4) = *(const float4*)(be2 + latb + 4);
#pragma unroll
        for (int j = 0; j < 8; j++) z[j] += bz[j];
#pragma unroll
        for (int j = 0; j < 8; j++) zsS[r * ZSTR + latb + j] = z[j];
        *(float4*)(out_z + (row0 + r) * LAT + latb)     = *(float4*)z;
        *(float4*)(out_z + (row0 + r) * LAT + latb + 4) = *(float4*)(z + 4);
    }
    __syncthreads();

    // ---- pn (shuffle-tree order) ----
    if (t < NPROTO) {
        const float* pj = prS + t * LAT;
        float a[32];
#pragma unroll
        for (int l = 0; l < 32; l++) a[l] = pj[l] * pj[l];
#pragma unroll
        for (int off = 16; off >= 1; off >>= 1)
#pragma unroll
            for (int i = 0; i < 16; i++)
                if (i < off) a[i] += a[i + off];
        pnS[t] = a[0];
    }
    __syncthreads();

    // ---- per-row argmin (reference form) + guard ----
    if (t < BMR) {
        const float* zr = zsS + t * ZSTR;
        float zz = 0.0f;
#pragma unroll
        for (int l = 0; l < LAT; l++) zz = fmaf(zr[l], zr[l], zz);
        float best = 3.4e38f, sec = 3.4e38f;
        int bi = 0;
#pragma unroll 1
        for (int j = 0; j < NPROTO; j++) {
            const float* pj = prS + j * LAT;
            float dot = 0.0f;
#pragma unroll
            for (int l = 0; l < LAT; l++) dot = fmaf(zr[l], pj[l], dot);
            float d = (zz - 2.0f * dot) + pnS[j];
            if (d < best) { sec = best; best = d; bi = j; }
            else if (d < sec) sec = d;
        }
        winS[t] = bi;
        if (sec - best < GUARD) {
            int idx = atomicAdd(&g_repair_count, 1);
            if (idx < BATCH) g_repair_rows[idx] = (int)(row0 + t);
        }
    }
    __syncthreads();

    // ---- som_z + x_recon (overlapped with other CTAs' GEMM) ----
    {
        float* out_som = out + (size_t)BATCH * (K1 + LAT);
        for (int idx = t; idx < BMR * LAT; idx += NTHR) {
            int rr = idx >> 5, l = idx & 31;
            out_som[(row0 + rr) * LAT + l] = prS[winS[rr] * LAT + l];
        }
        const float4* tab = (const float4*)g_recon_table4;
        float4* outr = (float4*)out;
        for (int idx = t; idx < BMR * (K1 / 4); idx += NTHR) {
            int rr = idx / (K1 / 4), q = idx - rr * (K1 / 4);
            outr[(row0 + rr) * (K1 / 4) + q] = tab[winS[rr] * (K1 / 4) + q];
        }
    }
}

// ---------------- repair kernel: exact fp32 path (R3/R4 order) ----------------
#define RROWS 8
__global__ void __launch_bounds__(256)
repair_kernel(const float* __restrict__ x,
              const float* __restrict__ We1,
              const float* __restrict__ be1,
              const float* __restrict__ We2,
              const float* __restrict__ be2,
              const float* __restrict__ proto,
              float* __restrict__ out) {
    __shared__ float xr[RROWS][K1];
    __shared__ float h8[RROWS][HID + 1];
    __shared__ float z8[RROWS][LAT];
    __shared__ float pp[32];
    __shared__ float dd[RROWS * 32];
    __shared__ int   rows[RROWS];
    __shared__ int   win8[RROWS];
    const int t = threadIdx.x;
    int cnt = g_repair_count;
    if (cnt > BATCH) cnt = BATCH;

    for (int g = blockIdx.x; g * RROWS < cnt; g += gridDim.x) {
        const int nr = min(RROWS, cnt - g * RROWS);
        if (t < nr) rows[t] = g_repair_rows[g * RROWS + t];
        __syncthreads();
        for (int i = t; i < nr * K1; i += 256) {
            int rr = i / K1, k = i - rr * K1;
            xr[rr][k] = x[(size_t)rows[rr] * K1 + k];
        }
        __syncthreads();
        // h: thread = hidden col, sequential k (R3 order); unroll 8 for MLP
        {
            float acc[RROWS];
#pragma unroll
            for (int rr = 0; rr < RROWS; rr++) acc[rr] = 0.0f;
#pragma unroll 1
            for (int k0 = 0; k0 < K1; k0 += 8) {
                float wv[8];
#pragma unroll
                for (int u = 0; u < 8; u++) wv[u] = We1[(k0 + u) * HID + t];
#pragma unroll
                for (int u = 0; u < 8; u++)
#pragma unroll
                    for (int rr = 0; rr < RROWS; rr++)
                        acc[rr] = fmaf(xr[rr][k0 + u], wv[u], acc[rr]);
            }
            float b = be1[t];
#pragma unroll
            for (int rr = 0; rr < RROWS; rr++)
                h8[rr][t] = fmaxf(acc[rr] + b, 0.0f);
        }
        __syncthreads();
        if (t < nr * LAT) {
            int rr = t >> 5, l = t & 31;
            float a = 0.0f;
#pragma unroll 8
            for (int n = 0; n < HID; n++) a = fmaf(h8[rr][n], We2[n * LAT + l], a);
            a += be2[l];
            z8[rr][l] = a;
            out[(size_t)BATCH * K1 + (size_t)rows[rr] * LAT + l] = a;
        }
        if (t >= 224 && t < 224 + NPROTO) {
            int j = t - 224;
            const float* pj = proto + j * LAT;
            float a[32];
#pragma unroll
            for (int l = 0; l < 32; l++) a[l] = pj[l] * pj[l];
#pragma unroll
            for (int off = 16; off >= 1; off >>= 1)
#pragma unroll
                for (int i = 0; i < 16; i++)
                    if (i < off) a[i] += a[i + off];
            pp[j] = a[0];
        }
        __syncthreads();
        if (t < nr * NPROTO) {
            int rr = t / NPROTO, j = t - rr * NPROTO;
            const float* zr = z8[rr];
            const float* pj = proto + j * LAT;
            float zz = 0.0f, dot = 0.0f;
#pragma unroll
            for (int l = 0; l < LAT; l++) zz = fmaf(zr[l], zr[l], zz);
#pragma unroll
            for (int l = 0; l < LAT; l++) dot = fmaf(zr[l], pj[l], dot);
            dd[rr * 32 + j] = (zz - 2.0f * dot) + pp[j];
        }
        __syncthreads();
        if (t < nr) {
            const float* dr = dd + t * 32;
            float best = dr[0];
            int bi = 0;
#pragma unroll
            for (int j = 1; j < NPROTO; j++) {
                float v = dr[j];
                if (v < best) { best = v; bi = j; }
            }
            win8[t] = bi;
        }
        __syncthreads();
        for (int i = t; i < nr * LAT; i += 256) {
            int rr = i >> 5, l = i & 31;
            out[(size_t)BATCH * (K1 + LAT) + (size_t)rows[rr] * LAT + l] =
                proto[win8[rr] * LAT + l];
        }
        const float4* tab = (const float4*)g_recon_table4;
        float4* outr = (float4*)out;
        for (int i = t; i < nr * (K1 / 4); i += 256) {
            int rr = i / (K1 / 4), q = i - rr * (K1 / 4);
            outr[(size_t)rows[rr] * (K1 / 4) + q] = tab[win8[rr] * (K1 / 4) + q];
        }
        __syncthreads();
    }
}

extern "C" void kernel_launch(void* const* d_in, const int* in_sizes, int n_in,
                              void* d_out, int out_size) {
    const float* x    = (const float*)d_in[0];
    const float* We1  = (const float*)d_in[1];
    const float* be1  = (const float*)d_in[2];
    const float* We2  = (const float*)d_in[3];
    const float* be2  = (const float*)d_in[4];
    const float* Wd1  = (const float*)d_in[5];
    const float* bd1  = (const float*)d_in[6];
    const float* Wd2  = (const float*)d_in[7];
    const float* bd2  = (const float*)d_in[8];
    const float* prot = (const float*)d_in[9];
    float* out = (float*)d_out;

    prep_w_kernel<<<NCH, 256>>>(We1);
    decoder_table_kernel<<<dim3(NPROTO, 4), 256>>>(Wd1, bd1, Wd2, bd2, prot);

    cudaFuncSetAttribute(dpsom_fused_kernel,
                         cudaFuncAttributeMaxDynamicSharedMemorySize, SMEM_BYTES);
    dpsom_fused_kernel<<<BATCH / BMR, NTHR, SMEM_BYTES>>>(x, be1, We2, be2, prot, out);

    repair_kernel<<<512, 256>>>(x, We1, be1, We2, be2, prot, out);
}

// round 12
// speedup vs baseline: 1.6587x; 1.1233x over previous
#include <cuda_runtime.h>
#include <cuda_fp16.h>

// ---------------------------------------------------------------------------
// DPSOM, round 12.  vs R11 (441.8us; repair 127us INVARIANT to grid size =>
// per-group latency-bound on the un-staged We1 load chain):
//  * repair kernel rewritten: We1 streamed in 32-row chunks into smem
//    cooperatively (float4, MLP 8), FMAs read smem; We2 staged once per
//    block.  Per-thread k-order unchanged (strictly ascending) -> winners
//    bit-identical to the R3-proven exact path.
//  * fused kernel / prep / GUARD identical to R11 (isolate one change).
//   output layout: [x_recon (B*784) | z (B*32) | som_z (B*32)]  (fp32)
// ---------------------------------------------------------------------------

#define BATCH   65536
#define K1      784
#define HID     256
#define LAT     32
#define NPROTO  25
#define BMR     64
#define NTHR    256
#define NCH     13
#define VCH     26
#define GUARD   1e-2f

// fused smem bytes: [0..1024) be1; A stage 8KB @1024; B stages 32KB @9216+
#define ABASE    1024
#define BBASE    9216
#define HS_OFF   256
#define HSTR     257
#define WE2_OFF  16704
#define ZS_OFF   24896
#define ZSTR     33
#define PR_OFF   27008
#define PN_OFF   27808
#define WIN_OFF  27840
#define SMEM_FLOATS 27904
#define SMEM_BYTES  (SMEM_FLOATS * 4)   // 111616

// repair smem layout (floats)
#define RROWS    8
#define RXR      0                       // [8][784]
#define RW1      6272                    // [32][256]
#define RWE2     14464                   // [256][32]
#define RH8      22656                   // [8][257]
#define RZ8      24712                   // [8][32]
#define RPP      24968                   // [32]
#define RDD      25000                   // [8*32]
#define RROWSI   25256                   // int[8]
#define RWINI    25264                   // int[8]
#define RSM_FLOATS 25272
#define RSM_BYTES  (RSM_FLOATS * 4)      // 101088

typedef unsigned long long u64;
typedef unsigned int u32;

__device__ uint4  g_Bhi[NCH * 2048];   // fp16 W_hi, [c][n*8 + swizzled-j]
__device__ uint4  g_Blo[NCH * 2048];   // fp16 W_lo
__device__ float4 g_recon_table4[NPROTO * (K1 / 4)];
__device__ int    g_repair_count;
__device__ int    g_repair_rows[BATCH];

__host__ __device__ __forceinline__ u32 swz(u32 b) { return b ^ ((b >> 3) & 0x70); }

__device__ __forceinline__ u32 su(const void* p) {
    u32 a;
    asm("{ .reg .u64 t; cvta.to.shared.u64 t, %1; cvt.u32.u64 %0, t; }" : "=r"(a) : "l"(p));
    return a;
}
__device__ __forceinline__ void ldsm4(u32 a, u32& r0, u32& r1, u32& r2, u32& r3) {
    asm volatile("ldmatrix.sync.aligned.m8n8.x4.shared.b16 {%0,%1,%2,%3}, [%4];"
                 : "=r"(r0), "=r"(r1), "=r"(r2), "=r"(r3) : "r"(a));
}
__device__ __forceinline__ void mma16816h(float* c, const u32* a, u32 b0, u32 b1) {
    asm volatile("mma.sync.aligned.m16n8k16.row.col.f32.f16.f16.f32 "
                 "{%0,%1,%2,%3},{%4,%5,%6,%7},{%8,%9},{%0,%1,%2,%3};"
                 : "+f"(c[0]), "+f"(c[1]), "+f"(c[2]), "+f"(c[3])
                 : "r"(a[0]), "r"(a[1]), "r"(a[2]), "r"(a[3]), "r"(b0), "r"(b1));
}
__device__ __forceinline__ void cpasync16(u32 dst, const void* src) {
    asm volatile("cp.async.cg.shared.global [%0], [%1], 16;" :: "r"(dst), "l"(src));
}
#define CP_COMMIT() asm volatile("cp.async.commit_group;")
#define CP_WAIT0()  asm volatile("cp.async.wait_group 0;")
#define CP_WAIT1()  asm volatile("cp.async.wait_group 1;")

__device__ __forceinline__ u32 pack2h(float a, float b) {
    __half ha = __float2half_rn(a), hb = __float2half_rn(b);
    return (u32)__half_as_ushort(ha) | ((u32)__half_as_ushort(hb) << 16);
}

// ---------------- prep kernels ----------------
__global__ void prep_w_kernel(const float* __restrict__ We1) {
    const int c = blockIdx.x;       // 13
    const int n = threadIdx.x;      // 256
    if (c == 0 && n == 0) g_repair_count = 0;
    u32 hw[32], lw[32];
#pragma unroll 4
    for (int kp = 0; kp < 64; kp += 2) {
        int k0 = c * 64 + kp;
        float v0 = (k0 < K1)     ? We1[(size_t)k0 * HID + n] : 0.0f;
        float v1 = (k0 + 1 < K1) ? We1[(size_t)(k0 + 1) * HID + n] : 0.0f;
        __half h0 = __float2half_rn(v0), h1 = __float2half_rn(v1);
        float l0f = v0 - __half2float(h0), l1f = v1 - __half2float(h1);
        __half l0 = __float2half_rn(l0f), l1 = __float2half_rn(l1f);
        hw[kp >> 1] = (u32)__half_as_ushort(h0) | ((u32)__half_as_ushort(h1) << 16);
        lw[kp >> 1] = (u32)__half_as_ushort(l0) | ((u32)__half_as_ushort(l1) << 16);
    }
#pragma unroll
    for (int j = 0; j < 8; j++) {
        int jd = j ^ (n & 7);      // 128B-row swizzle (R9-R11 proven)
        g_Bhi[c * 2048 + n * 8 + jd] = make_uint4(hw[j*4], hw[j*4+1], hw[j*4+2], hw[j*4+3]);
        g_Blo[c * 2048 + n * 8 + jd] = make_uint4(lw[j*4], lw[j*4+1], lw[j*4+2], lw[j*4+3]);
    }
}

__global__ void decoder_table_kernel(const float* __restrict__ Wd1,
                                     const float* __restrict__ bd1,
                                     const float* __restrict__ Wd2,
                                     const float* __restrict__ bd2,
                                     const float* __restrict__ proto) {
    __shared__ float p[LAT];
    __shared__ float hd[HID];
    const int pid = blockIdx.x;
    const int t = threadIdx.x;
    if (t < LAT) p[t] = proto[pid * LAT + t];
    __syncthreads();
    if (t < HID) {
        float acc = 0.0f;
#pragma unroll
        for (int l = 0; l < LAT; l++) acc = fmaf(p[l], Wd1[l * HID + t], acc);
        hd[t] = fmaxf(acc + bd1[t], 0.0f);
    }
    __syncthreads();
    float* gt = (float*)g_recon_table4;
    int o = blockIdx.y * 196 + t;
    if (t < 196) {
        float acc = 0.0f;
#pragma unroll 8
        for (int n = 0; n < HID; n++) acc = fmaf(hd[n], Wd2[n * K1 + o], acc);
        float v = acc + bd2[o];
        gt[pid * K1 + o] = 1.0f / (1.0f + expf(-v));
    }
}

// ---------------- fused kernel (identical to R11) ----------------
__global__ void __launch_bounds__(NTHR, 2)
dpsom_fused_kernel(const float* __restrict__ x,
                   const float* __restrict__ be1,
                   const float* __restrict__ We2,
                   const float* __restrict__ be2,
                   const float* __restrict__ proto,
                   float* __restrict__ out) {
    extern __shared__ float sm[];
    const u32 sb = su(sm);
    const int t = threadIdx.x, lane = t & 31, w = t >> 5;
    const int wn0 = w * 32;
    const size_t row0 = (size_t)blockIdx.x * BMR;

    const int ar = t >> 2, aq = t & 3;
    const u32 bn  = (u32)((lane & 7) + ((lane & 16) ? 8 : 0));
    const u32 bkb = (u32)(((lane >> 3) & 1) * 16);

    sm[t] = be1[t];

    u32 va[8];
    auto loadA = [&](int ca) {
        const float4* xp = (const float4*)(x + (row0 + ar) * K1 + ca * 64 + aq * 16);
#pragma unroll
        for (int j = 0; j < 4; j++) {
            int kk = ca * 64 + aq * 16 + j * 4;
            float4 v = (kk < K1) ? xp[j] : make_float4(0.f, 0.f, 0.f, 0.f);
            va[j * 2]     = pack2h(v.x, v.y);
            va[j * 2 + 1] = pack2h(v.z, v.w);
        }
    };
    auto storeA = [&]() {
        char* Sb = (char*)sm + ABASE;
#pragma unroll
        for (int j = 0; j < 4; j++) {
            u32 o = swz((u32)ar * 128u + (u32)((aq * 16 + j * 4) * 2));
            *(uint2*)(Sb + o) = make_uint2(va[j * 2], va[j * 2 + 1]);
        }
    };
    auto loadB = [&](int vc) {
        const uint4* src = ((vc & 1) ? g_Blo : g_Bhi) + (vc >> 1) * 2048;
        u32 dst = sb + BBASE + (u32)(vc % 3) * 32768u;
#pragma unroll
        for (int j = 0; j < 8; j++) {
            int o = j * NTHR + t;
            cpasync16(dst + o * 16, src + o);
        }
        CP_COMMIT();
    };

    loadA(0); storeA(); loadB(0); loadB(1);
    CP_WAIT1();
    __syncthreads();

    float acc[4][4][4];
#pragma unroll
    for (int m = 0; m < 4; m++)
#pragma unroll
        for (int n = 0; n < 4; n++)
#pragma unroll
            for (int q = 0; q < 4; q++) acc[m][n][q] = 0.0f;

#pragma unroll 1
    for (int vc = 0; vc < VCH; vc++) {
        if (vc + 2 < VCH) loadB(vc + 2);
        const int c = vc >> 1;
        if (((vc & 1) == 0) && (c + 1 < NCH)) loadA(c + 1);

        const u32 Ab = sb + ABASE;
        const u32 Bb = sb + BBASE + (u32)(vc % 3) * 32768u;
#pragma unroll
        for (int ks = 0; ks < 4; ks++) {
            const u32 kb = (u32)ks * 32u;
            u32 ah[16];
#pragma unroll
            for (int m = 0; m < 4; m++) {
                u32 o = (u32)((m * 16 + (lane & 15)) * 128) + ((u32)(lane >> 4) << 4) + kb;
                ldsm4(Ab + swz(o), ah[m*4+0], ah[m*4+1], ah[m*4+2], ah[m*4+3]);
            }
            u32 bb[8];
#pragma unroll
            for (int pr = 0; pr < 2; pr++) {
                u32 o = (u32)((wn0 + pr * 16 + bn) * 128) + kb + bkb;
                ldsm4(Bb + swz(o), bb[pr*4+0], bb[pr*4+1], bb[pr*4+2], bb[pr*4+3]);
            }
#pragma unroll
            for (int m = 0; m < 4; m++)
#pragma unroll
                for (int nt = 0; nt < 4; nt++)
                    mma16816h(acc[m][nt], &ah[m * 4],
                              bb[(nt >> 1) * 4 + (nt & 1) * 2],
                              bb[(nt >> 1) * 4 + (nt & 1) * 2 + 1]);
        }
        if (((vc & 1) == 1) && (c + 1 < NCH)) {
            __syncthreads();
            storeA();
        }
        if (vc + 2 < VCH) CP_WAIT1(); else CP_WAIT0();
        __syncthreads();
    }

    float* hS = sm + HS_OFF;
    {
        const int g = lane >> 2, tq = (lane & 3) * 2;
#pragma unroll
        for (int m = 0; m < 4; m++)
#pragma unroll
            for (int nt = 0; nt < 4; nt++) {
                int row = m * 16 + g;
                int col = wn0 + nt * 8 + tq;
                float b0 = sm[col], b1 = sm[col + 1];
                float* cc = acc[m][nt];
                hS[row * HSTR + col]           = fmaxf(cc[0] + b0, 0.0f);
                hS[row * HSTR + col + 1]       = fmaxf(cc[1] + b1, 0.0f);
                hS[(row + 8) * HSTR + col]     = fmaxf(cc[2] + b0, 0.0f);
                hS[(row + 8) * HSTR + col + 1] = fmaxf(cc[3] + b1, 0.0f);
            }
    }
    float* we2s = sm + WE2_OFF;
    float* zsS  = sm + ZS_OFF;
    float* prS  = sm + PR_OFF;
    float* pnS  = sm + PN_OFF;
    int*   winS = (int*)(sm + WIN_OFF);
    for (int i = t; i < HID * LAT; i += NTHR) we2s[i] = We2[i];
    for (int i = t; i < NPROTO * LAT; i += NTHR) prS[i] = proto[i];
    __syncthreads();

    {
        float* out_z = out + (size_t)BATCH * K1;
        const int r = t >> 2;
        const int latb = (t & 3) * 8;
        u64 a0 = 0, a1 = 0, a2 = 0, a3 = 0;
        const float* hr = hS + r * HSTR;
        const float* wbase = we2s + latb;
#pragma unroll 8
        for (int n = 0; n < HID; n++) {
            float hv = hr[n];
            u64 hd;
            asm("mov.b64 %0,{%1,%1};" : "=l"(hd) : "f"(hv));
            ulonglong2 w0 = *(const ulonglong2*)(wbase + n * LAT);
            ulonglong2 w1 = *(const ulonglong2*)(wbase + n * LAT + 4);
            asm("fma.rn.f32x2 %0, %1, %2, %0;" : "+l"(a0) : "l"(hd), "l"(w0.x));
            asm("fma.rn.f32x2 %0, %1, %2, %0;" : "+l"(a1) : "l"(hd), "l"(w0.y));
            asm("fma.rn.f32x2 %0, %1, %2, %0;" : "+l"(a2) : "l"(hd), "l"(w1.x));
            asm("fma.rn.f32x2 %0, %1, %2, %0;" : "+l"(a3) : "l"(hd), "l"(w1.y));
        }
        float z[8];
        asm("mov.b64 {%0,%1},%2;" : "=f"(z[0]), "=f"(z[1]) : "l"(a0));
        asm("mov.b64 {%0,%1},%2;" : "=f"(z[2]), "=f"(z[3]) : "l"(a1));
        asm("mov.b64 {%0,%1},%2;" : "=f"(z[4]), "=f"(z[5]) : "l"(a2));
        asm("mov.b64 {%0,%1},%2;" : "=f"(z[6]), "=f"(z[7]) : "l"(a3));
        float bz[8];
        *(float4*)bz       = *(const float4*)(be2 + latb);
        *(float4*)(bz + 4) = *(const float4*)(be2 + latb + 4);
#pragma unroll
        for (int j = 0; j < 8; j++) z[j] += bz[j];
#pragma unroll
        for (int j = 0; j < 8; j++) zsS[r * ZSTR + latb + j] = z[j];
        *(float4*)(out_z + (row0 + r) * LAT + latb)     = *(float4*)z;
        *(float4*)(out_z + (row0 + r) * LAT + latb + 4) = *(float4*)(z + 4);
    }
    __syncthreads();

    if (t < NPROTO) {
        const float* pj = prS + t * LAT;
        float a[32];
#pragma unroll
        for (int l = 0; l < 32; l++) a[l] = pj[l] * pj[l];
#pragma unroll
        for (int off = 16; off >= 1; off >>= 1)
#pragma unroll
            for (int i = 0; i < 16; i++)
                if (i < off) a[i] += a[i + off];
        pnS[t] = a[0];
    }
    __syncthreads();

    if (t < BMR) {
        const float* zr = zsS + t * ZSTR;
        float zz = 0.0f;
#pragma unroll
        for (int l = 0; l < LAT; l++) zz = fmaf(zr[l], zr[l], zz);
        float best = 3.4e38f, sec = 3.4e38f;
        int bi = 0;
#pragma unroll 1
        for (int j = 0; j < NPROTO; j++) {
            const float* pj = prS + j * LAT;
            float dot = 0.0f;
#pragma unroll
            for (int l = 0; l < LAT; l++) dot = fmaf(zr[l], pj[l], dot);
            float d = (zz - 2.0f * dot) + pnS[j];
            if (d < best) { sec = best; best = d; bi = j; }
            else if (d < sec) sec = d;
        }
        winS[t] = bi;
        if (sec - best < GUARD) {
            int idx = atomicAdd(&g_repair_count, 1);
            if (idx < BATCH) g_repair_rows[idx] = (int)(row0 + t);
        }
    }
    __syncthreads();

    {
        float* out_som = out + (size_t)BATCH * (K1 + LAT);
        for (int idx = t; idx < BMR * LAT; idx += NTHR) {
            int rr = idx >> 5, l = idx & 31;
            out_som[(row0 + rr) * LAT + l] = prS[winS[rr] * LAT + l];
        }
        const float4* tab = (const float4*)g_recon_table4;
        float4* outr = (float4*)out;
        for (int idx = t; idx < BMR * (K1 / 4); idx += NTHR) {
            int rr = idx / (K1 / 4), q = idx - rr * (K1 / 4);
            outr[(row0 + rr) * (K1 / 4) + q] = tab[winS[rr] * (K1 / 4) + q];
        }
    }
}

// ---------------- repair kernel v2: smem-staged, order-preserving ----------------
__global__ void __launch_bounds__(256)
repair_kernel(const float* __restrict__ x,
              const float* __restrict__ We1,
              const float* __restrict__ be1,
              const float* __restrict__ We2,
              const float* __restrict__ be2,
              const float* __restrict__ proto,
              float* __restrict__ out) {
    extern __shared__ float rsm[];
    float* xr   = rsm + RXR;      // [8][784]
    float* w1s  = rsm + RW1;      // [32][256]
    float* we2s = rsm + RWE2;     // [256][32]
    float* h8   = rsm + RH8;      // [8][257]
    float* z8   = rsm + RZ8;      // [8][32]
    float* pp   = rsm + RPP;      // [32]
    float* dd   = rsm + RDD;      // [8][32]
    int* rows   = (int*)(rsm + RROWSI);
    int* win8   = (int*)(rsm + RWINI);
    const int t = threadIdx.x;
    int cnt = g_repair_count;
    if (cnt > BATCH) cnt = BATCH;
    if (blockIdx.x * RROWS >= cnt) return;   // idle blocks exit immediately

    // stage We2 (32KB) once per block, float4 coalesced
    {
        const float4* s = (const float4*)We2;
        float4* d = (float4*)we2s;
        for (int i = t; i < HID * LAT / 4; i += 256) d[i] = s[i];
    }
    // pp (shuffle-tree order, R3-proven)
    if (t < NPROTO) {
        const float* pj = proto + t * LAT;
        float a[32];
#pragma unroll
        for (int l = 0; l < 32; l++) a[l] = pj[l] * pj[l];
#pragma unroll
        for (int off = 16; off >= 1; off >>= 1)
#pragma unroll
            for (int i = 0; i < 16; i++)
                if (i < off) a[i] += a[i + off];
        pp[t] = a[0];
    }

    for (int g = blockIdx.x; g * RROWS < cnt; g += gridDim.x) {
        const int nr = min(RROWS, cnt - g * RROWS);
        __syncthreads();                       // prev group done with rows/xr
        if (t < nr) rows[t] = g_repair_rows[g * RROWS + t];
        __syncthreads();
        // x rows, float4 coalesced
        for (int i = t; i < nr * (K1 / 4); i += 256) {
            int rr = i / (K1 / 4), q = i - rr * (K1 / 4);
            ((float4*)(xr + rr * K1))[q] = ((const float4*)(x + (size_t)rows[rr] * K1))[q];
        }

        // ---- GEMM1: stream We1 in 32-row smem chunks; k ascending per thread ----
        float acc[RROWS];
#pragma unroll
        for (int rr = 0; rr < RROWS; rr++) acc[rr] = 0.0f;
#pragma unroll 1
        for (int kc = 0; kc < 768; kc += 32) {
            __syncthreads();                   // w1s free (also covers xr 1st iter)
            {
                const float4* s = (const float4*)(We1 + kc * HID);
                float4* d = (float4*)w1s;
#pragma unroll
                for (int j = 0; j < 8; j++) d[j * 256 + t] = s[j * 256 + t];
            }
            __syncthreads();
#pragma unroll
            for (int u = 0; u < 32; u++) {
                float wv = w1s[u * HID + t];
#pragma unroll
                for (int rr = 0; rr < RROWS; rr++)
                    acc[rr] = fmaf(xr[rr * K1 + kc + u], wv, acc[rr]);
            }
        }
        // tail chunk: k = 768..783 (16 rows)
        {
            __syncthreads();
            const float4* s = (const float4*)(We1 + 768 * HID);
            float4* d = (float4*)w1s;
#pragma unroll
            for (int j = 0; j < 4; j++) d[j * 256 + t] = s[j * 256 + t];
            __syncthreads();
#pragma unroll
            for (int u = 0; u < 16; u++) {
                float wv = w1s[u * HID + t];
#pragma unroll
                for (int rr = 0; rr < RROWS; rr++)
                    acc[rr] = fmaf(xr[rr * K1 + 768 + u], wv, acc[rr]);
            }
        }
        {
            float b = be1[t];
#pragma unroll
            for (int rr = 0; rr < RROWS; rr++)
                h8[rr * 257 + t] = fmaxf(acc[rr] + b, 0.0f);
        }
        __syncthreads();

        // ---- GEMM2 (LDS-only): t -> (row rr, lat l); sequential n ----
        if (t < nr * LAT) {
            int rr = t >> 5, l = t & 31;
            float a = 0.0f;
#pragma unroll 8
            for (int n = 0; n < HID; n++)
                a = fmaf(h8[rr * 257 + n], we2s[n * LAT + l], a);
            a += be2[l];
            z8[rr * LAT + l] = a;
            out[(size_t)BATCH * K1 + (size_t)rows[rr] * LAT + l] = a;
        }
        __syncthreads();
        // ---- distances (reference form) + argmin ----
        if (t < nr * NPROTO) {
            int rr = t / NPROTO, j = t - rr * NPROTO;
            const float* zr = z8 + rr * LAT;
            const float* pj = proto + j * LAT;
            float zz = 0.0f, dot = 0.0f;
#pragma unroll
            for (int l = 0; l < LAT; l++) zz = fmaf(zr[l], zr[l], zz);
#pragma unroll
            for (int l = 0; l < LAT; l++) dot = fmaf(zr[l], pj[l], dot);
            dd[rr * 32 + j] = (zz - 2.0f * dot) + pp[j];
        }
        __syncthreads();
        if (t < nr) {
            const float* dr = dd + t * 32;
            float best = dr[0];
            int bi = 0;
#pragma unroll
            for (int j = 1; j < NPROTO; j++) {
                float v = dr[j];
                if (v < best) { best = v; bi = j; }
            }
            win8[t] = bi;
        }
        __syncthreads();
        for (int i = t; i < nr * LAT; i += 256) {
            int rr = i >> 5, l = i & 31;
            out[(size_t)BATCH * (K1 + LAT) + (size_t)rows[rr] * LAT + l] =
                proto[win8[rr] * LAT + l];
        }
        const float4* tab = (const float4*)g_recon_table4;
        float4* outr = (float4*)out;
        for (int i = t; i < nr * (K1 / 4); i += 256) {
            int rr = i / (K1 / 4), q = i - rr * (K1 / 4);
            outr[(size_t)rows[rr] * (K1 / 4) + q] = tab[win8[rr] * (K1 / 4) + q];
        }
    }
}

extern "C" void kernel_launch(void* const* d_in, const int* in_sizes, int n_in,
                              void* d_out, int out_size) {
    const float* x    = (const float*)d_in[0];
    const float* We1  = (const float*)d_in[1];
    const float* be1  = (const float*)d_in[2];
    const float* We2  = (const float*)d_in[3];
    const float* be2  = (const float*)d_in[4];
    const float* Wd1  = (const float*)d_in[5];
    const float* bd1  = (const float*)d_in[6];
    const float* Wd2  = (const float*)d_in[7];
    const float* bd2  = (const float*)d_in[8];
    const float* prot = (const float*)d_in[9];
    float* out = (float*)d_out;

    prep_w_kernel<<<NCH, 256>>>(We1);
    decoder_table_kernel<<<dim3(NPROTO, 4), 256>>>(Wd1, bd1, Wd2, bd2, prot);

    cudaFuncSetAttribute(dpsom_fused_kernel,
                         cudaFuncAttributeMaxDynamicSharedMemorySize, SMEM_BYTES);
    dpsom_fused_kernel<<<BATCH / BMR, NTHR, SMEM_BYTES>>>(x, be1, We2, be2, prot, out);

    cudaFuncSetAttribute(repair_kernel,
                         cudaFuncAttributeMaxDynamicSharedMemorySize, RSM_BYTES);
    repair_kernel<<<512, 256, RSM_BYTES>>>(x, We1, be1, We2, be2, prot, out);
}

// round 13
// speedup vs baseline: 1.6806x; 1.0132x over previous
#include <cuda_runtime.h>
#include <cuda_fp16.h>

// ---------------------------------------------------------------------------
// DPSOM, round 13.  vs R12 (393.3us; repair 72.9us = serial chunk loop with
// exposed L2 latency):
//  * repair: We1 staged via cp.async into a 2x32KB ping-pong; chunk k+1
//    streams while chunk k computes.  Per-thread k-order unchanged
//    (ascending) -> winners bit-identical.
//  * fused kernel / prep / GUARD byte-identical to R12 (isolate one change).
//   output layout: [x_recon (B*784) | z (B*32) | som_z (B*32)]  (fp32)
// ---------------------------------------------------------------------------

#define BATCH   65536
#define K1      784
#define HID     256
#define LAT     32
#define NPROTO  25
#define BMR     64
#define NTHR    256
#define NCH     13
#define VCH     26
#define GUARD   1e-2f

// fused smem bytes: [0..1024) be1; A stage 8KB @1024; B stages 32KB @9216+
#define ABASE    1024
#define BBASE    9216
#define HS_OFF   256
#define HSTR     257
#define WE2_OFF  16704
#define ZS_OFF   24896
#define ZSTR     33
#define PR_OFF   27008
#define PN_OFF   27808
#define WIN_OFF  27840
#define SMEM_FLOATS 27904
#define SMEM_BYTES  (SMEM_FLOATS * 4)   // 111616

// repair smem layout (floats)
#define RROWS    8
#define RXR      0                       // [8][784]
#define RW1      6272                    // 2 x [32][256] ping-pong
#define RWE2     22656                   // [256][32]
#define RH8      30848                   // [8][257]
#define RZ8      32904                   // [8][32]
#define RPP      33160                   // [32]
#define RDD      33192                   // [8*32]
#define RROWSI   33448                   // int[8]
#define RWINI    33456                   // int[8]
#define RSM_FLOATS 33464
#define RSM_BYTES  (RSM_FLOATS * 4)      // 133856

typedef unsigned long long u64;
typedef unsigned int u32;

__device__ uint4  g_Bhi[NCH * 2048];   // fp16 W_hi, [c][n*8 + swizzled-j]
__device__ uint4  g_Blo[NCH * 2048];   // fp16 W_lo
__device__ float4 g_recon_table4[NPROTO * (K1 / 4)];
__device__ int    g_repair_count;
__device__ int    g_repair_rows[BATCH];

__host__ __device__ __forceinline__ u32 swz(u32 b) { return b ^ ((b >> 3) & 0x70); }

__device__ __forceinline__ u32 su(const void* p) {
    u32 a;
    asm("{ .reg .u64 t; cvta.to.shared.u64 t, %1; cvt.u32.u64 %0, t; }" : "=r"(a) : "l"(p));
    return a;
}
__device__ __forceinline__ void ldsm4(u32 a, u32& r0, u32& r1, u32& r2, u32& r3) {
    asm volatile("ldmatrix.sync.aligned.m8n8.x4.shared.b16 {%0,%1,%2,%3}, [%4];"
                 : "=r"(r0), "=r"(r1), "=r"(r2), "=r"(r3) : "r"(a));
}
__device__ __forceinline__ void mma16816h(float* c, const u32* a, u32 b0, u32 b1) {
    asm volatile("mma.sync.aligned.m16n8k16.row.col.f32.f16.f16.f32 "
                 "{%0,%1,%2,%3},{%4,%5,%6,%7},{%8,%9},{%0,%1,%2,%3};"
                 : "+f"(c[0]), "+f"(c[1]), "+f"(c[2]), "+f"(c[3])
                 : "r"(a[0]), "r"(a[1]), "r"(a[2]), "r"(a[3]), "r"(b0), "r"(b1));
}
__device__ __forceinline__ void cpasync16(u32 dst, const void* src) {
    asm volatile("cp.async.cg.shared.global [%0], [%1], 16;" :: "r"(dst), "l"(src));
}
#define CP_COMMIT() asm volatile("cp.async.commit_group;")
#define CP_WAIT0()  asm volatile("cp.async.wait_group 0;")
#define CP_WAIT1()  asm volatile("cp.async.wait_group 1;")

__device__ __forceinline__ u32 pack2h(float a, float b) {
    __half ha = __float2half_rn(a), hb = __float2half_rn(b);
    return (u32)__half_as_ushort(ha) | ((u32)__half_as_ushort(hb) << 16);
}

// ---------------- prep kernels (identical to R12) ----------------
__global__ void prep_w_kernel(const float* __restrict__ We1) {
    const int c = blockIdx.x;
    const int n = threadIdx.x;
    if (c == 0 && n == 0) g_repair_count = 0;
    u32 hw[32], lw[32];
#pragma unroll 4
    for (int kp = 0; kp < 64; kp += 2) {
        int k0 = c * 64 + kp;
        float v0 = (k0 < K1)     ? We1[(size_t)k0 * HID + n] : 0.0f;
        float v1 = (k0 + 1 < K1) ? We1[(size_t)(k0 + 1) * HID + n] : 0.0f;
        __half h0 = __float2half_rn(v0), h1 = __float2half_rn(v1);
        float l0f = v0 - __half2float(h0), l1f = v1 - __half2float(h1);
        __half l0 = __float2half_rn(l0f), l1 = __float2half_rn(l1f);
        hw[kp >> 1] = (u32)__half_as_ushort(h0) | ((u32)__half_as_ushort(h1) << 16);
        lw[kp >> 1] = (u32)__half_as_ushort(l0) | ((u32)__half_as_ushort(l1) << 16);
    }
#pragma unroll
    for (int j = 0; j < 8; j++) {
        int jd = j ^ (n & 7);
        g_Bhi[c * 2048 + n * 8 + jd] = make_uint4(hw[j*4], hw[j*4+1], hw[j*4+2], hw[j*4+3]);
        g_Blo[c * 2048 + n * 8 + jd] = make_uint4(lw[j*4], lw[j*4+1], lw[j*4+2], lw[j*4+3]);
    }
}

__global__ void decoder_table_kernel(const float* __restrict__ Wd1,
                                     const float* __restrict__ bd1,
                                     const float* __restrict__ Wd2,
                                     const float* __restrict__ bd2,
                                     const float* __restrict__ proto) {
    __shared__ float p[LAT];
    __shared__ float hd[HID];
    const int pid = blockIdx.x;
    const int t = threadIdx.x;
    if (t < LAT) p[t] = proto[pid * LAT + t];
    __syncthreads();
    if (t < HID) {
        float acc = 0.0f;
#pragma unroll
        for (int l = 0; l < LAT; l++) acc = fmaf(p[l], Wd1[l * HID + t], acc);
        hd[t] = fmaxf(acc + bd1[t], 0.0f);
    }
    __syncthreads();
    float* gt = (float*)g_recon_table4;
    int o = blockIdx.y * 196 + t;
    if (t < 196) {
        float acc = 0.0f;
#pragma unroll 8
        for (int n = 0; n < HID; n++) acc = fmaf(hd[n], Wd2[n * K1 + o], acc);
        float v = acc + bd2[o];
        gt[pid * K1 + o] = 1.0f / (1.0f + expf(-v));
    }
}

// ---------------- fused kernel (identical to R11/R12) ----------------
__global__ void __launch_bounds__(NTHR, 2)
dpsom_fused_kernel(const float* __restrict__ x,
                   const float* __restrict__ be1,
                   const float* __restrict__ We2,
                   const float* __restrict__ be2,
                   const float* __restrict__ proto,
                   float* __restrict__ out) {
    extern __shared__ float sm[];
    const u32 sb = su(sm);
    const int t = threadIdx.x, lane = t & 31, w = t >> 5;
    const int wn0 = w * 32;
    const size_t row0 = (size_t)blockIdx.x * BMR;

    const int ar = t >> 2, aq = t & 3;
    const u32 bn  = (u32)((lane & 7) + ((lane & 16) ? 8 : 0));
    const u32 bkb = (u32)(((lane >> 3) & 1) * 16);

    sm[t] = be1[t];

    u32 va[8];
    auto loadA = [&](int ca) {
        const float4* xp = (const float4*)(x + (row0 + ar) * K1 + ca * 64 + aq * 16);
#pragma unroll
        for (int j = 0; j < 4; j++) {
            int kk = ca * 64 + aq * 16 + j * 4;
            float4 v = (kk < K1) ? xp[j] : make_float4(0.f, 0.f, 0.f, 0.f);
            va[j * 2]     = pack2h(v.x, v.y);
            va[j * 2 + 1] = pack2h(v.z, v.w);
        }
    };
    auto storeA = [&]() {
        char* Sb = (char*)sm + ABASE;
#pragma unroll
        for (int j = 0; j < 4; j++) {
            u32 o = swz((u32)ar * 128u + (u32)((aq * 16 + j * 4) * 2));
            *(uint2*)(Sb + o) = make_uint2(va[j * 2], va[j * 2 + 1]);
        }
    };
    auto loadB = [&](int vc) {
        const uint4* src = ((vc & 1) ? g_Blo : g_Bhi) + (vc >> 1) * 2048;
        u32 dst = sb + BBASE + (u32)(vc % 3) * 32768u;
#pragma unroll
        for (int j = 0; j < 8; j++) {
            int o = j * NTHR + t;
            cpasync16(dst + o * 16, src + o);
        }
        CP_COMMIT();
    };

    loadA(0); storeA(); loadB(0); loadB(1);
    CP_WAIT1();
    __syncthreads();

    float acc[4][4][4];
#pragma unroll
    for (int m = 0; m < 4; m++)
#pragma unroll
        for (int n = 0; n < 4; n++)
#pragma unroll
            for (int q = 0; q < 4; q++) acc[m][n][q] = 0.0f;

#pragma unroll 1
    for (int vc = 0; vc < VCH; vc++) {
        if (vc + 2 < VCH) loadB(vc + 2);
        const int c = vc >> 1;
        if (((vc & 1) == 0) && (c + 1 < NCH)) loadA(c + 1);

        const u32 Ab = sb + ABASE;
        const u32 Bb = sb + BBASE + (u32)(vc % 3) * 32768u;
#pragma unroll
        for (int ks = 0; ks < 4; ks++) {
            const u32 kb = (u32)ks * 32u;
            u32 ah[16];
#pragma unroll
            for (int m = 0; m < 4; m++) {
                u32 o = (u32)((m * 16 + (lane & 15)) * 128) + ((u32)(lane >> 4) << 4) + kb;
                ldsm4(Ab + swz(o), ah[m*4+0], ah[m*4+1], ah[m*4+2], ah[m*4+3]);
            }
            u32 bb[8];
#pragma unroll
            for (int pr = 0; pr < 2; pr++) {
                u32 o = (u32)((wn0 + pr * 16 + bn) * 128) + kb + bkb;
                ldsm4(Bb + swz(o), bb[pr*4+0], bb[pr*4+1], bb[pr*4+2], bb[pr*4+3]);
            }
#pragma unroll
            for (int m = 0; m < 4; m++)
#pragma unroll
                for (int nt = 0; nt < 4; nt++)
                    mma16816h(acc[m][nt], &ah[m * 4],
                              bb[(nt >> 1) * 4 + (nt & 1) * 2],
                              bb[(nt >> 1) * 4 + (nt & 1) * 2 + 1]);
        }
        if (((vc & 1) == 1) && (c + 1 < NCH)) {
            __syncthreads();
            storeA();
        }
        if (vc + 2 < VCH) CP_WAIT1(); else CP_WAIT0();
        __syncthreads();
    }

    float* hS = sm + HS_OFF;
    {
        const int g = lane >> 2, tq = (lane & 3) * 2;
#pragma unroll
        for (int m = 0; m < 4; m++)
#pragma unroll
            for (int nt = 0; nt < 4; nt++) {
                int row = m * 16 + g;
                int col = wn0 + nt * 8 + tq;
                float b0 = sm[col], b1 = sm[col + 1];
                float* cc = acc[m][nt];
                hS[row * HSTR + col]           = fmaxf(cc[0] + b0, 0.0f);
                hS[row * HSTR + col + 1]       = fmaxf(cc[1] + b1, 0.0f);
                hS[(row + 8) * HSTR + col]     = fmaxf(cc[2] + b0, 0.0f);
                hS[(row + 8) * HSTR + col + 1] = fmaxf(cc[3] + b1, 0.0f);
            }
    }
    float* we2s = sm + WE2_OFF;
    float* zsS  = sm + ZS_OFF;
    float* prS  = sm + PR_OFF;
    float* pnS  = sm + PN_OFF;
    int*   winS = (int*)(sm + WIN_OFF);
    for (int i = t; i < HID * LAT; i += NTHR) we2s[i] = We2[i];
    for (int i = t; i < NPROTO * LAT; i += NTHR) prS[i] = proto[i];
    __syncthreads();

    {
        float* out_z = out + (size_t)BATCH * K1;
        const int r = t >> 2;
        const int latb = (t & 3) * 8;
        u64 a0 = 0, a1 = 0, a2 = 0, a3 = 0;
        const float* hr = hS + r * HSTR;
        const float* wbase = we2s + latb;
#pragma unroll 8
        for (int n = 0; n < HID; n++) {
            float hv = hr[n];
            u64 hd;
            asm("mov.b64 %0,{%1,%1};" : "=l"(hd) : "f"(hv));
            ulonglong2 w0 = *(const ulonglong2*)(wbase + n * LAT);
            ulonglong2 w1 = *(const ulonglong2*)(wbase + n * LAT + 4);
            asm("fma.rn.f32x2 %0, %1, %2, %0;" : "+l"(a0) : "l"(hd), "l"(w0.x));
            asm("fma.rn.f32x2 %0, %1, %2, %0;" : "+l"(a1) : "l"(hd), "l"(w0.y));
            asm("fma.rn.f32x2 %0, %1, %2, %0;" : "+l"(a2) : "l"(hd), "l"(w1.x));
            asm("fma.rn.f32x2 %0, %1, %2, %0;" : "+l"(a3) : "l"(hd), "l"(w1.y));
        }
        float z[8];
        asm("mov.b64 {%0,%1},%2;" : "=f"(z[0]), "=f"(z[1]) : "l"(a0));
        asm("mov.b64 {%0,%1},%2;" : "=f"(z[2]), "=f"(z[3]) : "l"(a1));
        asm("mov.b64 {%0,%1},%2;" : "=f"(z[4]), "=f"(z[5]) : "l"(a2));
        asm("mov.b64 {%0,%1},%2;" : "=f"(z[6]), "=f"(z[7]) : "l"(a3));
        float bz[8];
        *(float4*)bz       = *(const float4*)(be2 + latb);
        *(float4*)(bz + 4) = *(const float4*)(be2 + latb + 4);
#pragma unroll
        for (int j = 0; j < 8; j++) z[j] += bz[j];
#pragma unroll
        for (int j = 0; j < 8; j++) zsS[r * ZSTR + latb + j] = z[j];
        *(float4*)(out_z + (row0 + r) * LAT + latb)     = *(float4*)z;
        *(float4*)(out_z + (row0 + r) * LAT + latb + 4) = *(float4*)(z + 4);
    }
    __syncthreads();

    if (t < NPROTO) {
        const float* pj = prS + t * LAT;
        float a[32];
#pragma unroll
        for (int l = 0; l < 32; l++) a[l] = pj[l] * pj[l];
#pragma unroll
        for (int off = 16; off >= 1; off >>= 1)
#pragma unroll
            for (int i = 0; i < 16; i++)
                if (i < off) a[i] += a[i + off];
        pnS[t] = a[0];
    }
    __syncthreads();

    if (t < BMR) {
        const float* zr = zsS + t * ZSTR;
        float zz = 0.0f;
#pragma unroll
        for (int l = 0; l < LAT; l++) zz = fmaf(zr[l], zr[l], zz);
        float best = 3.4e38f, sec = 3.4e38f;
        int bi = 0;
#pragma unroll 1
        for (int j = 0; j < NPROTO; j++) {
            const float* pj = prS + j * LAT;
            float dot = 0.0f;
#pragma unroll
            for (int l = 0; l < LAT; l++) dot = fmaf(zr[l], pj[l], dot);
            float d = (zz - 2.0f * dot) + pnS[j];
            if (d < best) { sec = best; best = d; bi = j; }
            else if (d < sec) sec = d;
        }
        winS[t] = bi;
        if (sec - best < GUARD) {
            int idx = atomicAdd(&g_repair_count, 1);
            if (idx < BATCH) g_repair_rows[idx] = (int)(row0 + t);
        }
    }
    __syncthreads();

    {
        float* out_som = out + (size_t)BATCH * (K1 + LAT);
        for (int idx = t; idx < BMR * LAT; idx += NTHR) {
            int rr = idx >> 5, l = idx & 31;
            out_som[(row0 + rr) * LAT + l] = prS[winS[rr] * LAT + l];
        }
        const float4* tab = (const float4*)g_recon_table4;
        float4* outr = (float4*)out;
        for (int idx = t; idx < BMR * (K1 / 4); idx += NTHR) {
            int rr = idx / (K1 / 4), q = idx - rr * (K1 / 4);
            outr[(row0 + rr) * (K1 / 4) + q] = tab[winS[rr] * (K1 / 4) + q];
        }
    }
}

// ---------------- repair kernel v3: cp.async double-buffered We1 ----------------
__global__ void __launch_bounds__(256)
repair_kernel(const float* __restrict__ x,
              const float* __restrict__ We1,
              const float* __restrict__ be1,
              const float* __restrict__ We2,
              const float* __restrict__ be2,
              const float* __restrict__ proto,
              float* __restrict__ out) {
    extern __shared__ float rsm[];
    float* xr   = rsm + RXR;
    float* w1s  = rsm + RW1;      // 2 x [32][256] ping-pong
    float* we2s = rsm + RWE2;
    float* h8   = rsm + RH8;
    float* z8   = rsm + RZ8;
    float* pp   = rsm + RPP;
    float* dd   = rsm + RDD;
    int* rows   = (int*)(rsm + RROWSI);
    int* win8   = (int*)(rsm + RWINI);
    const int t = threadIdx.x;
    const u32 w1b = su(w1s);
    int cnt = g_repair_count;
    if (cnt > BATCH) cnt = BATCH;
    if (blockIdx.x * RROWS >= cnt) return;

    // issue chunk-kc We1 rows into ping-pong buffer (kc & 1). 25 chunks:
    // kc 0..23 -> 32 rows, kc 24 -> 16 rows.
    auto issueW1 = [&](int kc) {
        int nrows = (kc == 24) ? 16 : 32;
        int units = nrows * 64;                 // 16B units (row = 64 units)
        const uint4* s = (const uint4*)(We1 + kc * 32 * HID);
        u32 d = w1b + (u32)(kc & 1) * 32768u;
        for (int i = t; i < units; i += 256) cpasync16(d + (u32)i * 16u, s + i);
        CP_COMMIT();
    };

    // stage We2 once per block
    {
        const float4* s = (const float4*)We2;
        float4* d = (float4*)we2s;
        for (int i = t; i < HID * LAT / 4; i += 256) d[i] = s[i];
    }
    if (t < NPROTO) {
        const float* pj = proto + t * LAT;
        float a[32];
#pragma unroll
        for (int l = 0; l < 32; l++) a[l] = pj[l] * pj[l];
#pragma unroll
        for (int off = 16; off >= 1; off >>= 1)
#pragma unroll
            for (int i = 0; i < 16; i++)
                if (i < off) a[i] += a[i + off];
        pp[t] = a[0];
    }

    for (int g = blockIdx.x; g * RROWS < cnt; g += gridDim.x) {
        const int nr = min(RROWS, cnt - g * RROWS);
        __syncthreads();
        if (t < nr) rows[t] = g_repair_rows[g * RROWS + t];
        __syncthreads();
        issueW1(0);
        for (int i = t; i < nr * (K1 / 4); i += 256) {
            int rr = i / (K1 / 4), q = i - rr * (K1 / 4);
            ((float4*)(xr + rr * K1))[q] = ((const float4*)(x + (size_t)rows[rr] * K1))[q];
        }
        issueW1(1);

        float acc[RROWS];
#pragma unroll
        for (int rr = 0; rr < RROWS; rr++) acc[rr] = 0.0f;

#pragma unroll 1
        for (int kc = 0; kc < 25; kc++) {
            // chunks kc, kc+1 outstanding -> wait for kc
            if (kc + 2 <= 24) CP_WAIT1(); else CP_WAIT0();
            __syncthreads();                    // chunk kc visible to all
            const float* wb = w1s + (kc & 1) * 8192;
            const int cs = (kc == 24) ? 16 : 32;
#pragma unroll 4
            for (int u = 0; u < cs; u++) {
                float wv = wb[u * HID + t];
#pragma unroll
                for (int rr = 0; rr < RROWS; rr++)
                    acc[rr] = fmaf(xr[rr * K1 + kc * 32 + u], wv, acc[rr]);
            }
            __syncthreads();                    // buffer (kc&1) free
            if (kc + 2 <= 24) issueW1(kc + 2);
        }
        {
            float b = be1[t];
#pragma unroll
            for (int rr = 0; rr < RROWS; rr++)
                h8[rr * 257 + t] = fmaxf(acc[rr] + b, 0.0f);
        }
        __syncthreads();

        if (t < nr * LAT) {
            int rr = t >> 5, l = t & 31;
            float a = 0.0f;
#pragma unroll 8
            for (int n = 0; n < HID; n++)
                a = fmaf(h8[rr * 257 + n], we2s[n * LAT + l], a);
            a += be2[l];
            z8[rr * LAT + l] = a;
            out[(size_t)BATCH * K1 + (size_t)rows[rr] * LAT + l] = a;
        }
        __syncthreads();
        if (t < nr * NPROTO) {
            int rr = t / NPROTO, j = t - rr * NPROTO;
            const float* zr = z8 + rr * LAT;
            const float* pj = proto + j * LAT;
            float zz = 0.0f, dot = 0.0f;
#pragma unroll
            for (int l = 0; l < LAT; l++) zz = fmaf(zr[l], zr[l], zz);
#pragma unroll
            for (int l = 0; l < LAT; l++) dot = fmaf(zr[l], pj[l], dot);
            dd[rr * 32 + j] = (zz - 2.0f * dot) + pp[j];
        }
        __syncthreads();
        if (t < nr) {
            const float* dr = dd + t * 32;
            float best = dr[0];
            int bi = 0;
#pragma unroll
            for (int j = 1; j < NPROTO; j++) {
                float v = dr[j];
                if (v < best) { best = v; bi = j; }
            }
            win8[t] = bi;
        }
        __syncthreads();
        for (int i = t; i < nr * LAT; i += 256) {
            int rr = i >> 5, l = i & 31;
            out[(size_t)BATCH * (K1 + LAT) + (size_t)rows[rr] * LAT + l] =
                proto[win8[rr] * LAT + l];
        }
        const float4* tab = (const float4*)g_recon_table4;
        float4* outr = (float4*)out;
        for (int i = t; i < nr * (K1 / 4); i += 256) {
            int rr = i / (K1 / 4), q = i - rr * (K1 / 4);
            outr[(size_t)rows[rr] * (K1 / 4) + q] = tab[win8[rr] * (K1 / 4) + q];
        }
    }
}

extern "C" void kernel_launch(void* const* d_in, const int* in_sizes, int n_in,
                              void* d_out, int out_size) {
    const float* x    = (const float*)d_in[0];
    const float* We1  = (const float*)d_in[1];
    const float* be1  = (const float*)d_in[2];
    const float* We2  = (const float*)d_in[3];
    const float* be2  = (const float*)d_in[4];
    const float* Wd1  = (const float*)d_in[5];
    const float* bd1  = (const float*)d_in[6];
    const float* Wd2  = (const float*)d_in[7];
    const float* bd2  = (const float*)d_in[8];
    const float* prot = (const float*)d_in[9];
    float* out = (float*)d_out;

    prep_w_kernel<<<NCH, 256>>>(We1);
    decoder_table_kernel<<<dim3(NPROTO, 4), 256>>>(Wd1, bd1, Wd2, bd2, prot);

    cudaFuncSetAttribute(dpsom_fused_kernel,
                         cudaFuncAttributeMaxDynamicSharedMemorySize, SMEM_BYTES);
    dpsom_fused_kernel<<<BATCH / BMR, NTHR, SMEM_BYTES>>>(x, be1, We2, be2, prot, out);

    cudaFuncSetAttribute(repair_kernel,
                         cudaFuncAttributeMaxDynamicSharedMemorySize, RSM_BYTES);
    repair_kernel<<<512, 256, RSM_BYTES>>>(x, We1, be1, We2, be2, prot, out);
}

// round 14
// speedup vs baseline: 1.7463x; 1.0391x over previous
#include <cuda_runtime.h>
#include <cuda_fp16.h>

// ---------------------------------------------------------------------------
// DPSOM, round 14.  vs R13 (388us; repair 63us = 2.5 waves @ 1 CTA/SM;
// fused ~310us with A fragments ldsm'd twice per chunk):
//  * fused mainloop: per-chunk restructure -- A fragments loaded ONCE per ks
//    and applied to both W_hi and W_lo (ldsm ops -33%, barriers 26->13).
//    3-buffer B ring kept; lo(c+1) prefetch issues end-of-c (2 CTAs/SM
//    cover the partial exposure).
//  * repair: smem 133.8KB -> 66.8KB (16-row We1 ping-pong chunks, We2 read
//    direct from L2 with unroll-8) => 3 CTAs/SM => single wave.
//   output layout: [x_recon (B*784) | z (B*32) | som_z (B*32)]  (fp32)
// ---------------------------------------------------------------------------

#define BATCH   65536
#define K1      784
#define HID     256
#define LAT     32
#define NPROTO  25
#define BMR     64
#define NTHR    256
#define NCH     13
#define VCH     26
#define GUARD   1e-2f

// fused smem bytes: [0..1024) be1; A stage 8KB @1024; B ring 3x32KB @9216+
#define ABASE    1024
#define BBASE    9216
#define HS_OFF   256
#define HSTR     257
#define WE2_OFF  16704
#define ZS_OFF   24896
#define ZSTR     33
#define PR_OFF   27008
#define PN_OFF   27808
#define WIN_OFF  27840
#define SMEM_FLOATS 27904
#define SMEM_BYTES  (SMEM_FLOATS * 4)   // 111616

// repair smem layout (floats) -- total 68320 B => 3 CTAs/SM
#define RROWS    8
#define RXR      0                       // [8][784]
#define RW1      6272                    // 2 x [16][256] ping-pong (16KB each)
#define RH8      14464                   // [8][257]
#define RZ8      16520                   // [8][32]
#define RPP      16776                   // [32]
#define RDD      16808                   // [8*32]
#define RROWSI   17064                   // int[8]
#define RWINI    17072                   // int[8]
#define RSM_FLOATS 17080
#define RSM_BYTES  (RSM_FLOATS * 4)      // 68320

typedef unsigned long long u64;
typedef unsigned int u32;

__device__ uint4  g_Bhi[NCH * 2048];   // fp16 W_hi, [c][n*8 + swizzled-j]
__device__ uint4  g_Blo[NCH * 2048];   // fp16 W_lo
__device__ float4 g_recon_table4[NPROTO * (K1 / 4)];
__device__ int    g_repair_count;
__device__ int    g_repair_rows[BATCH];

__host__ __device__ __forceinline__ u32 swz(u32 b) { return b ^ ((b >> 3) & 0x70); }

__device__ __forceinline__ u32 su(const void* p) {
    u32 a;
    asm("{ .reg .u64 t; cvta.to.shared.u64 t, %1; cvt.u32.u64 %0, t; }" : "=r"(a) : "l"(p));
    return a;
}
__device__ __forceinline__ void ldsm4(u32 a, u32& r0, u32& r1, u32& r2, u32& r3) {
    asm volatile("ldmatrix.sync.aligned.m8n8.x4.shared.b16 {%0,%1,%2,%3}, [%4];"
                 : "=r"(r0), "=r"(r1), "=r"(r2), "=r"(r3) : "r"(a));
}
__device__ __forceinline__ void mma16816h(float* c, const u32* a, u32 b0, u32 b1) {
    asm volatile("mma.sync.aligned.m16n8k16.row.col.f32.f16.f16.f32 "
                 "{%0,%1,%2,%3},{%4,%5,%6,%7},{%8,%9},{%0,%1,%2,%3};"
                 : "+f"(c[0]), "+f"(c[1]), "+f"(c[2]), "+f"(c[3])
                 : "r"(a[0]), "r"(a[1]), "r"(a[2]), "r"(a[3]), "r"(b0), "r"(b1));
}
__device__ __forceinline__ void cpasync16(u32 dst, const void* src) {
    asm volatile("cp.async.cg.shared.global [%0], [%1], 16;" :: "r"(dst), "l"(src));
}
#define CP_COMMIT() asm volatile("cp.async.commit_group;")
#define CP_WAIT0()  asm volatile("cp.async.wait_group 0;")
#define CP_WAIT1()  asm volatile("cp.async.wait_group 1;")

__device__ __forceinline__ u32 pack2h(float a, float b) {
    __half ha = __float2half_rn(a), hb = __float2half_rn(b);
    return (u32)__half_as_ushort(ha) | ((u32)__half_as_ushort(hb) << 16);
}

// ---------------- prep kernels (identical to R12/R13) ----------------
__global__ void prep_w_kernel(const float* __restrict__ We1) {
    const int c = blockIdx.x;
    const int n = threadIdx.x;
    if (c == 0 && n == 0) g_repair_count = 0;
    u32 hw[32], lw[32];
#pragma unroll 4
    for (int kp = 0; kp < 64; kp += 2) {
        int k0 = c * 64 + kp;
        float v0 = (k0 < K1)     ? We1[(size_t)k0 * HID + n] : 0.0f;
        float v1 = (k0 + 1 < K1) ? We1[(size_t)(k0 + 1) * HID + n] : 0.0f;
        __half h0 = __float2half_rn(v0), h1 = __float2half_rn(v1);
        float l0f = v0 - __half2float(h0), l1f = v1 - __half2float(h1);
        __half l0 = __float2half_rn(l0f), l1 = __float2half_rn(l1f);
        hw[kp >> 1] = (u32)__half_as_ushort(h0) | ((u32)__half_as_ushort(h1) << 16);
        lw[kp >> 1] = (u32)__half_as_ushort(l0) | ((u32)__half_as_ushort(l1) << 16);
    }
#pragma unroll
    for (int j = 0; j < 8; j++) {
        int jd = j ^ (n & 7);
        g_Bhi[c * 2048 + n * 8 + jd] = make_uint4(hw[j*4], hw[j*4+1], hw[j*4+2], hw[j*4+3]);
        g_Blo[c * 2048 + n * 8 + jd] = make_uint4(lw[j*4], lw[j*4+1], lw[j*4+2], lw[j*4+3]);
    }
}

__global__ void decoder_table_kernel(const float* __restrict__ Wd1,
                                     const float* __restrict__ bd1,
                                     const float* __restrict__ Wd2,
                                     const float* __restrict__ bd2,
                                     const float* __restrict__ proto) {
    __shared__ float p[LAT];
    __shared__ float hd[HID];
    const int pid = blockIdx.x;
    const int t = threadIdx.x;
    if (t < LAT) p[t] = proto[pid * LAT + t];
    __syncthreads();
    if (t < HID) {
        float acc = 0.0f;
#pragma unroll
        for (int l = 0; l < LAT; l++) acc = fmaf(p[l], Wd1[l * HID + t], acc);
        hd[t] = fmaxf(acc + bd1[t], 0.0f);
    }
    __syncthreads();
    float* gt = (float*)g_recon_table4;
    int o = blockIdx.y * 196 + t;
    if (t < 196) {
        float acc = 0.0f;
#pragma unroll 8
        for (int n = 0; n < HID; n++) acc = fmaf(hd[n], Wd2[n * K1 + o], acc);
        float v = acc + bd2[o];
        gt[pid * K1 + o] = 1.0f / (1.0f + expf(-v));
    }
}

// ---------------- fused kernel: per-chunk A-reuse mainloop ----------------
__global__ void __launch_bounds__(NTHR, 2)
dpsom_fused_kernel(const float* __restrict__ x,
                   const float* __restrict__ be1,
                   const float* __restrict__ We2,
                   const float* __restrict__ be2,
                   const float* __restrict__ proto,
                   float* __restrict__ out) {
    extern __shared__ float sm[];
    const u32 sb = su(sm);
    const int t = threadIdx.x, lane = t & 31, w = t >> 5;
    const int wn0 = w * 32;
    const size_t row0 = (size_t)blockIdx.x * BMR;

    const int ar = t >> 2, aq = t & 3;
    const u32 bn  = (u32)((lane & 7) + ((lane & 16) ? 8 : 0));
    const u32 bkb = (u32)(((lane >> 3) & 1) * 16);

    sm[t] = be1[t];

    u32 va[8];
    auto loadA = [&](int ca) {
        const float4* xp = (const float4*)(x + (row0 + ar) * K1 + ca * 64 + aq * 16);
#pragma unroll
        for (int j = 0; j < 4; j++) {
            int kk = ca * 64 + aq * 16 + j * 4;
            float4 v = (kk < K1) ? xp[j] : make_float4(0.f, 0.f, 0.f, 0.f);
            va[j * 2]     = pack2h(v.x, v.y);
            va[j * 2 + 1] = pack2h(v.z, v.w);
        }
    };
    auto storeA = [&]() {
        char* Sb = (char*)sm + ABASE;
#pragma unroll
        for (int j = 0; j < 4; j++) {
            u32 o = swz((u32)ar * 128u + (u32)((aq * 16 + j * 4) * 2));
            *(uint2*)(Sb + o) = make_uint2(va[j * 2], va[j * 2 + 1]);
        }
    };
    auto loadB = [&](int vc) {
        const uint4* src = ((vc & 1) ? g_Blo : g_Bhi) + (vc >> 1) * 2048;
        u32 dst = sb + BBASE + (u32)(vc % 3) * 32768u;
#pragma unroll
        for (int j = 0; j < 8; j++) {
            int o = j * NTHR + t;
            cpasync16(dst + o * 16, src + o);
        }
        CP_COMMIT();
    };

    // prologue: A chunk 0 staged; B vc0 (hi) + vc1 (lo) both complete
    loadA(0); storeA(); loadB(0); loadB(1);
    CP_WAIT0();
    __syncthreads();

    float acc[4][4][4];
#pragma unroll
    for (int m = 0; m < 4; m++)
#pragma unroll
        for (int n = 0; n < 4; n++)
#pragma unroll
            for (int q = 0; q < 4; q++) acc[m][n][q] = 0.0f;

#pragma unroll 1
    for (int c = 0; c < NCH; c++) {
        if (2 * c + 2 < VCH) loadB(2 * c + 2);      // buffer (2c+2)%3 free
        if (c + 1 < NCH) loadA(c + 1);

        const u32 Ab  = sb + ABASE;
        const u32 Bhi = sb + BBASE + (u32)((2 * c) % 3) * 32768u;
        const u32 Blo = sb + BBASE + (u32)((2 * c + 1) % 3) * 32768u;
#pragma unroll
        for (int ks = 0; ks < 4; ks++) {
            const u32 kb = (u32)ks * 32u;
            u32 ah[16];
#pragma unroll
            for (int m = 0; m < 4; m++) {
                u32 o = (u32)((m * 16 + (lane & 15)) * 128) + ((u32)(lane >> 4) << 4) + kb;
                ldsm4(Ab + swz(o), ah[m*4+0], ah[m*4+1], ah[m*4+2], ah[m*4+3]);
            }
            u32 bh[8], bl[8];
#pragma unroll
            for (int pr = 0; pr < 2; pr++) {
                u32 o = (u32)((wn0 + pr * 16 + bn) * 128) + kb + bkb;
                ldsm4(Bhi + swz(o), bh[pr*4+0], bh[pr*4+1], bh[pr*4+2], bh[pr*4+3]);
                ldsm4(Blo + swz(o), bl[pr*4+0], bl[pr*4+1], bl[pr*4+2], bl[pr*4+3]);
            }
#pragma unroll
            for (int m = 0; m < 4; m++)
#pragma unroll
                for (int nt = 0; nt < 4; nt++) {
                    float* cc = acc[m][nt];
                    int bi = (nt >> 1) * 4 + (nt & 1) * 2;
                    mma16816h(cc, &ah[m * 4], bh[bi], bh[bi + 1]);
                    mma16816h(cc, &ah[m * 4], bl[bi], bl[bi + 1]);
                }
        }
        if (c + 1 < NCH) {
            __syncthreads();        // all warps done with A stage + Bhi buffer
            storeA();
            loadB(2 * c + 3);       // buffer (2c+3)%3 == (2c)%3, now free
        }
        CP_WAIT0();
        __syncthreads();
    }

    // ---- h = relu(acc + be1) -> hS; stages dead ----
    float* hS = sm + HS_OFF;
    {
        const int g = lane >> 2, tq = (lane & 3) * 2;
#pragma unroll
        for (int m = 0; m < 4; m++)
#pragma unroll
            for (int nt = 0; nt < 4; nt++) {
                int row = m * 16 + g;
                int col = wn0 + nt * 8 + tq;
                float b0 = sm[col], b1 = sm[col + 1];
                float* cc = acc[m][nt];
                hS[row * HSTR + col]           = fmaxf(cc[0] + b0, 0.0f);
                hS[row * HSTR + col + 1]       = fmaxf(cc[1] + b1, 0.0f);
                hS[(row + 8) * HSTR + col]     = fmaxf(cc[2] + b0, 0.0f);
                hS[(row + 8) * HSTR + col + 1] = fmaxf(cc[3] + b1, 0.0f);
            }
    }
    float* we2s = sm + WE2_OFF;
    float* zsS  = sm + ZS_OFF;
    float* prS  = sm + PR_OFF;
    float* pnS  = sm + PN_OFF;
    int*   winS = (int*)(sm + WIN_OFF);
    for (int i = t; i < HID * LAT; i += NTHR) we2s[i] = We2[i];
    for (int i = t; i < NPROTO * LAT; i += NTHR) prS[i] = proto[i];
    __syncthreads();

    {
        float* out_z = out + (size_t)BATCH * K1;
        const int r = t >> 2;
        const int latb = (t & 3) * 8;
        u64 a0 = 0, a1 = 0, a2 = 0, a3 = 0;
        const float* hr = hS + r * HSTR;
        const float* wbase = we2s + latb;
#pragma unroll 8
        for (int n = 0; n < HID; n++) {
            float hv = hr[n];
            u64 hd;
            asm("mov.b64 %0,{%1,%1};" : "=l"(hd) : "f"(hv));
            ulonglong2 w0 = *(const ulonglong2*)(wbase + n * LAT);
            ulonglong2 w1 = *(const ulonglong2*)(wbase + n * LAT + 4);
            asm("fma.rn.f32x2 %0, %1, %2, %0;" : "+l"(a0) : "l"(hd), "l"(w0.x));
            asm("fma.rn.f32x2 %0, %1, %2, %0;" : "+l"(a1) : "l"(hd), "l"(w0.y));
            asm("fma.rn.f32x2 %0, %1, %2, %0;" : "+l"(a2) : "l"(hd), "l"(w1.x));
            asm("fma.rn.f32x2 %0, %1, %2, %0;" : "+l"(a3) : "l"(hd), "l"(w1.y));
        }
        float z[8];
        asm("mov.b64 {%0,%1},%2;" : "=f"(z[0]), "=f"(z[1]) : "l"(a0));
        asm("mov.b64 {%0,%1},%2;" : "=f"(z[2]), "=f"(z[3]) : "l"(a1));
        asm("mov.b64 {%0,%1},%2;" : "=f"(z[4]), "=f"(z[5]) : "l"(a2));
        asm("mov.b64 {%0,%1},%2;" : "=f"(z[6]), "=f"(z[7]) : "l"(a3));
        float bz[8];
        *(float4*)bz       = *(const float4*)(be2 + latb);
        *(float4*)(bz + 4) = *(const float4*)(be2 + latb + 4);
#pragma unroll
        for (int j = 0; j < 8; j++) z[j] += bz[j];
#pragma unroll
        for (int j = 0; j < 8; j++) zsS[r * ZSTR + latb + j] = z[j];
        *(float4*)(out_z + (row0 + r) * LAT + latb)     = *(float4*)z;
        *(float4*)(out_z + (row0 + r) * LAT + latb + 4) = *(float4*)(z + 4);
    }
    __syncthreads();

    if (t < NPROTO) {
        const float* pj = prS + t * LAT;
        float a[32];
#pragma unroll
        for (int l = 0; l < 32; l++) a[l] = pj[l] * pj[l];
#pragma unroll
        for (int off = 16; off >= 1; off >>= 1)
#pragma unroll
            for (int i = 0; i < 16; i++)
                if (i < off) a[i] += a[i + off];
        pnS[t] = a[0];
    }
    __syncthreads();

    if (t < BMR) {
        const float* zr = zsS + t * ZSTR;
        float zz = 0.0f;
#pragma unroll
        for (int l = 0; l < LAT; l++) zz = fmaf(zr[l], zr[l], zz);
        float best = 3.4e38f, sec = 3.4e38f;
        int bi = 0;
#pragma unroll 1
        for (int j = 0; j < NPROTO; j++) {
            const float* pj = prS + j * LAT;
            float dot = 0.0f;
#pragma unroll
            for (int l = 0; l < LAT; l++) dot = fmaf(zr[l], pj[l], dot);
            float d = (zz - 2.0f * dot) + pnS[j];
            if (d < best) { sec = best; best = d; bi = j; }
            else if (d < sec) sec = d;
        }
        winS[t] = bi;
        if (sec - best < GUARD) {
            int idx = atomicAdd(&g_repair_count, 1);
            if (idx < BATCH) g_repair_rows[idx] = (int)(row0 + t);
        }
    }
    __syncthreads();

    {
        float* out_som = out + (size_t)BATCH * (K1 + LAT);
        for (int idx = t; idx < BMR * LAT; idx += NTHR) {
            int rr = idx >> 5, l = idx & 31;
            out_som[(row0 + rr) * LAT + l] = prS[winS[rr] * LAT + l];
        }
        const float4* tab = (const float4*)g_recon_table4;
        float4* outr = (float4*)out;
        for (int idx = t; idx < BMR * (K1 / 4); idx += NTHR) {
            int rr = idx / (K1 / 4), q = idx - rr * (K1 / 4);
            outr[(row0 + rr) * (K1 / 4) + q] = tab[winS[rr] * (K1 / 4) + q];
        }
    }
}

// ---------------- repair kernel v4: 66.8KB smem -> 3 CTAs/SM ----------------
__global__ void __launch_bounds__(256, 3)
repair_kernel(const float* __restrict__ x,
              const float* __restrict__ We1,
              const float* __restrict__ be1,
              const float* __restrict__ We2,
              const float* __restrict__ be2,
              const float* __restrict__ proto,
              float* __restrict__ out) {
    extern __shared__ float rsm[];
    float* xr   = rsm + RXR;
    float* w1s  = rsm + RW1;      // 2 x [16][256] ping-pong
    float* h8   = rsm + RH8;
    float* z8   = rsm + RZ8;
    float* pp   = rsm + RPP;
    float* dd   = rsm + RDD;
    int* rows   = (int*)(rsm + RROWSI);
    int* win8   = (int*)(rsm + RWINI);
    const int t = threadIdx.x;
    const u32 w1b = su(w1s);
    int cnt = g_repair_count;
    if (cnt > BATCH) cnt = BATCH;
    if (blockIdx.x * RROWS >= cnt) return;

    // issue 16-row We1 chunk kc into ping-pong (kc & 1); 49 chunks total.
    auto issueW1 = [&](int kc) {
        const uint4* s = (const uint4*)(We1 + kc * 16 * HID);
        u32 d = w1b + (u32)(kc & 1) * 16384u;
#pragma unroll
        for (int j = 0; j < 4; j++) cpasync16(d + (u32)(j * 256 + t) * 16u, s + j * 256 + t);
        CP_COMMIT();
    };

    if (t < NPROTO) {
        const float* pj = proto + t * LAT;
        float a[32];
#pragma unroll
        for (int l = 0; l < 32; l++) a[l] = pj[l] * pj[l];
#pragma unroll
        for (int off = 16; off >= 1; off >>= 1)
#pragma unroll
            for (int i = 0; i < 16; i++)
                if (i < off) a[i] += a[i + off];
        pp[t] = a[0];
    }

    for (int g = blockIdx.x; g * RROWS < cnt; g += gridDim.x) {
        const int nr = min(RROWS, cnt - g * RROWS);
        __syncthreads();
        if (t < nr) rows[t] = g_repair_rows[g * RROWS + t];
        __syncthreads();
        issueW1(0);
        for (int i = t; i < nr * (K1 / 4); i += 256) {
            int rr = i / (K1 / 4), q = i - rr * (K1 / 4);
            ((float4*)(xr + rr * K1))[q] = ((const float4*)(x + (size_t)rows[rr] * K1))[q];
        }
        issueW1(1);

        float acc[RROWS];
#pragma unroll
        for (int rr = 0; rr < RROWS; rr++) acc[rr] = 0.0f;

#pragma unroll 1
        for (int kc = 0; kc < 49; kc++) {
            if (kc + 2 <= 48) CP_WAIT1(); else CP_WAIT0();
            __syncthreads();
            const float* wb = w1s + (kc & 1) * 4096;
#pragma unroll 4
            for (int u = 0; u < 16; u++) {
                float wv = wb[u * HID + t];
#pragma unroll
                for (int rr = 0; rr < RROWS; rr++)
                    acc[rr] = fmaf(xr[rr * K1 + kc * 16 + u], wv, acc[rr]);
            }
            __syncthreads();
            if (kc + 2 <= 48) issueW1(kc + 2);
        }
        {
            float b = be1[t];
#pragma unroll
            for (int rr = 0; rr < RROWS; rr++)
                h8[rr * 257 + t] = fmaxf(acc[rr] + b, 0.0f);
        }
        __syncthreads();

        // GEMM2: We2 direct from L2, unroll 8 for MLP; sequential n order.
        if (t < nr * LAT) {
            int rr = t >> 5, l = t & 31;
            float a = 0.0f;
#pragma unroll 8
            for (int n = 0; n < HID; n++)
                a = fmaf(h8[rr * 257 + n], We2[n * LAT + l], a);
            a += be2[l];
            z8[rr * LAT + l] = a;
            out[(size_t)BATCH * K1 + (size_t)rows[rr] * LAT + l] = a;
        }
        __syncthreads();
        if (t < nr * NPROTO) {
            int rr = t / NPROTO, j = t - rr * NPROTO;
            const float* zr = z8 + rr * LAT;
            const float* pj = proto + j * LAT;
            float zz = 0.0f, dot = 0.0f;
#pragma unroll
            for (int l = 0; l < LAT; l++) zz = fmaf(zr[l], zr[l], zz);
#pragma unroll
            for (int l = 0; l < LAT; l++) dot = fmaf(zr[l], pj[l], dot);
            dd[rr * 32 + j] = (zz - 2.0f * dot) + pp[j];
        }
        __syncthreads();
        if (t < nr) {
            const float* dr = dd + t * 32;
            float best = dr[0];
            int bi = 0;
#pragma unroll
            for (int j = 1; j < NPROTO; j++) {
                float v = dr[j];
                if (v < best) { best = v; bi = j; }
            }
            win8[t] = bi;
        }
        __syncthreads();
        for (int i = t; i < nr * LAT; i += 256) {
            int rr = i >> 5, l = i & 31;
            out[(size_t)BATCH * (K1 + LAT) + (size_t)rows[rr] * LAT + l] =
                proto[win8[rr] * LAT + l];
        }
        const float4* tab = (const float4*)g_recon_table4;
        float4* outr = (float4*)out;
        for (int i = t; i < nr * (K1 / 4); i += 256) {
            int rr = i / (K1 / 4), q = i - rr * (K1 / 4);
            outr[(size_t)rows[rr] * (K1 / 4) + q] = tab[win8[rr] * (K1 / 4) + q];
        }
    }
}

extern "C" void kernel_launch(void* const* d_in, const int* in_sizes, int n_in,
                              void* d_out, int out_size) {
    const float* x    = (const float*)d_in[0];
    const float* We1  = (const float*)d_in[1];
    const float* be1  = (const float*)d_in[2];
    const float* We2  = (const float*)d_in[3];
    const float* be2  = (const float*)d_in[4];
    const float* Wd1  = (const float*)d_in[5];
    const float* bd1  = (const float*)d_in[6];
    const float* Wd2  = (const float*)d_in[7];
    const float* bd2  = (const float*)d_in[8];
    const float* prot = (const float*)d_in[9];
    float* out = (float*)d_out;

    prep_w_kernel<<<NCH, 256>>>(We1);
    decoder_table_kernel<<<dim3(NPROTO, 4), 256>>>(Wd1, bd1, Wd2, bd2, prot);

    cudaFuncSetAttribute(dpsom_fused_kernel,
                         cudaFuncAttributeMaxDynamicSharedMemorySize, SMEM_BYTES);
    dpsom_fused_kernel<<<BATCH / BMR, NTHR, SMEM_BYTES>>>(x, be1, We2, be2, prot, out);

    cudaFuncSetAttribute(repair_kernel,
                         cudaFuncAttributeMaxDynamicSharedMemorySize, RSM_BYTES);
    repair_kernel<<<512, 256, RSM_BYTES>>>(x, We1, be1, We2, be2, prot, out);
}

// round 17
// speedup vs baseline: 1.9279x; 1.1040x over previous
#include <cuda_runtime.h>
#include <cuda_fp16.h>

// ---------------------------------------------------------------------------
// DPSOM, round 17 (= R16 resubmitted; R16 hit "GB300 container failed twice"
// and never ran).  R15's bug: SMEM_BYTES (104960) < B-ring end (107520);
// fixed here via SMEM_FLOATS 26880.  Logic:
//  * GEMM2 via register-reuse HMMA: GEMM1 C fragments bias+relu'd and packed
//    to fp16 A fragments in registers; B = We2 pre-split fp16 (hi+lo) in the
//    GEMM1-proven swizzled tile format; per-warp K=32 partials, 8-warp reduce.
//  * repair (cp.async We1 ping-pong, 3 CTAs/SM) and prep as R14.
//   output layout: [x_recon (B*784) | z (B*32) | som_z (B*32)]  (fp32)
// ---------------------------------------------------------------------------

#define BATCH   65536
#define K1      784
#define HID     256
#define LAT     32
#define NPROTO  25
#define BMR     64
#define NTHR    256
#define NCH     13
#define VCH     26
#define GUARD   1e-2f

// fused smem: [0..1024)B be1; A stage 8KB @1024B; B ring 3x32KB @9216B
// (ends 107520B).  epilogue (floats, aliases stages):
#define ABASE    1024
#define BBASE    9216
#define ZP_OFF   256                    // [8][64][33] fp32 partials -> 17152
#define ZSTR     33
#define W2T_OFF  17152                  // fp16 We2T hi 16KB + lo 16KB
#define W2T_BYTE (W2T_OFF * 4)          // 68608
#define PR_OFF   25344
#define PN_OFF   26144
#define WIN_OFF  26176
#define SMEM_FLOATS 26880               // 107520 B = B-ring end
#define SMEM_BYTES  (SMEM_FLOATS * 4)

// repair smem layout (floats) -- identical to R14
#define RROWS    8
#define RXR      0
#define RW1      6272
#define RH8      14464
#define RZ8      16520
#define RPP      16776
#define RDD      16808
#define RROWSI   17064
#define RWINI    17072
#define RSM_FLOATS 17080
#define RSM_BYTES  (RSM_FLOATS * 4)      // 68320

typedef unsigned long long u64;
typedef unsigned int u32;

__device__ uint4  g_Bhi[NCH * 2048];
__device__ uint4  g_Blo[NCH * 2048];
__device__ uint4  g_W2Thi[1024];        // [4 tiles][32 n][128B swizzled]
__device__ uint4  g_W2Tlo[1024];
__device__ float4 g_recon_table4[NPROTO * (K1 / 4)];
__device__ int    g_repair_count;
__device__ int    g_repair_rows[BATCH];

__host__ __device__ __forceinline__ u32 swz(u32 b) { return b ^ ((b >> 3) & 0x70); }

__device__ __forceinline__ u32 su(const void* p) {
    u32 a;
    asm("{ .reg .u64 t; cvta.to.shared.u64 t, %1; cvt.u32.u64 %0, t; }" : "=r"(a) : "l"(p));
    return a;
}
__device__ __forceinline__ void ldsm4(u32 a, u32& r0, u32& r1, u32& r2, u32& r3) {
    asm volatile("ldmatrix.sync.aligned.m8n8.x4.shared.b16 {%0,%1,%2,%3}, [%4];"
                 : "=r"(r0), "=r"(r1), "=r"(r2), "=r"(r3) : "r"(a));
}
__device__ __forceinline__ void mma16816h(float* c, const u32* a, u32 b0, u32 b1) {
    asm volatile("mma.sync.aligned.m16n8k16.row.col.f32.f16.f16.f32 "
                 "{%0,%1,%2,%3},{%4,%5,%6,%7},{%8,%9},{%0,%1,%2,%3};"
                 : "+f"(c[0]), "+f"(c[1]), "+f"(c[2]), "+f"(c[3])
                 : "r"(a[0]), "r"(a[1]), "r"(a[2]), "r"(a[3]), "r"(b0), "r"(b1));
}
__device__ __forceinline__ void cpasync16(u32 dst, const void* src) {
    asm volatile("cp.async.cg.shared.global [%0], [%1], 16;" :: "r"(dst), "l"(src));
}
#define CP_COMMIT() asm volatile("cp.async.commit_group;")
#define CP_WAIT0()  asm volatile("cp.async.wait_group 0;")
#define CP_WAIT1()  asm volatile("cp.async.wait_group 1;")

__device__ __forceinline__ u32 pack2h(float a, float b) {
    __half ha = __float2half_rn(a), hb = __float2half_rn(b);
    return (u32)__half_as_ushort(ha) | ((u32)__half_as_ushort(hb) << 16);
}

// ---------------- prep kernels ----------------
__global__ void prep_w_kernel(const float* __restrict__ We1) {
    const int c = blockIdx.x;
    const int n = threadIdx.x;
    if (c == 0 && n == 0) g_repair_count = 0;
    u32 hw[32], lw[32];
#pragma unroll 4
    for (int kp = 0; kp < 64; kp += 2) {
        int k0 = c * 64 + kp;
        float v0 = (k0 < K1)     ? We1[(size_t)k0 * HID + n] : 0.0f;
        float v1 = (k0 + 1 < K1) ? We1[(size_t)(k0 + 1) * HID + n] : 0.0f;
        __half h0 = __float2half_rn(v0), h1 = __float2half_rn(v1);
        float l0f = v0 - __half2float(h0), l1f = v1 - __half2float(h1);
        __half l0 = __float2half_rn(l0f), l1 = __float2half_rn(l1f);
        hw[kp >> 1] = (u32)__half_as_ushort(h0) | ((u32)__half_as_ushort(h1) << 16);
        lw[kp >> 1] = (u32)__half_as_ushort(l0) | ((u32)__half_as_ushort(l1) << 16);
    }
#pragma unroll
    for (int j = 0; j < 8; j++) {
        int jd = j ^ (n & 7);
        g_Bhi[c * 2048 + n * 8 + jd] = make_uint4(hw[j*4], hw[j*4+1], hw[j*4+2], hw[j*4+3]);
        g_Blo[c * 2048 + n * 8 + jd] = make_uint4(lw[j*4], lw[j*4+1], lw[j*4+2], lw[j*4+3]);
    }
}

// We2T: [n=32][k=256] fp16 hi/lo in 4 swizzled 32x64 tiles (GEMM1 B format)
__global__ void prep_we2t_kernel(const float* __restrict__ We2) {
    const int t = threadIdx.x;
    __half* bh = (__half*)g_W2Thi;
    __half* bl = (__half*)g_W2Tlo;
    for (int i = t; i < HID * LAT; i += 256) {
        int k = i >> 5, n = i & 31;               // We2[k][n]
        float v = We2[i];
        __half hi = __float2half_rn(v);
        __half lo = __float2half_rn(v - __half2float(hi));
        int tile = k >> 6, kp = k & 63;
        u32 off = (u32)tile * 4096u + swz((u32)(n * 128 + kp * 2));
        bh[off >> 1] = hi;
        bl[off >> 1] = lo;
    }
}

__global__ void decoder_table_kernel(const float* __restrict__ Wd1,
                                     const float* __restrict__ bd1,
                                     const float* __restrict__ Wd2,
                                     const float* __restrict__ bd2,
                                     const float* __restrict__ proto) {
    __shared__ float p[LAT];
    __shared__ float hd[HID];
    const int pid = blockIdx.x;
    const int t = threadIdx.x;
    if (t < LAT) p[t] = proto[pid * LAT + t];
    __syncthreads();
    if (t < HID) {
        float acc = 0.0f;
#pragma unroll
        for (int l = 0; l < LAT; l++) acc = fmaf(p[l], Wd1[l * HID + t], acc);
        hd[t] = fmaxf(acc + bd1[t], 0.0f);
    }
    __syncthreads();
    float* gt = (float*)g_recon_table4;
    int o = blockIdx.y * 196 + t;
    if (t < 196) {
        float acc = 0.0f;
#pragma unroll 8
        for (int n = 0; n < HID; n++) acc = fmaf(hd[n], Wd2[n * K1 + o], acc);
        float v = acc + bd2[o];
        gt[pid * K1 + o] = 1.0f / (1.0f + expf(-v));
    }
}

// ---------------- fused kernel ----------------
__global__ void __launch_bounds__(NTHR, 2)
dpsom_fused_kernel(const float* __restrict__ x,
                   const float* __restrict__ be1,
                   const float* __restrict__ be2,
                   const float* __restrict__ proto,
                   float* __restrict__ out) {
    extern __shared__ float sm[];
    const u32 sb = su(sm);
    const int t = threadIdx.x, lane = t & 31, w = t >> 5;
    const int wn0 = w * 32;
    const size_t row0 = (size_t)blockIdx.x * BMR;

    const int ar = t >> 2, aq = t & 3;
    const u32 bn  = (u32)((lane & 7) + ((lane & 16) ? 8 : 0));
    const u32 bkb = (u32)(((lane >> 3) & 1) * 16);

    sm[t] = be1[t];

    u32 va[8];
    auto loadA = [&](int ca) {
        const float4* xp = (const float4*)(x + (row0 + ar) * K1 + ca * 64 + aq * 16);
#pragma unroll
        for (int j = 0; j < 4; j++) {
            int kk = ca * 64 + aq * 16 + j * 4;
            float4 v = (kk < K1) ? xp[j] : make_float4(0.f, 0.f, 0.f, 0.f);
            va[j * 2]     = pack2h(v.x, v.y);
            va[j * 2 + 1] = pack2h(v.z, v.w);
        }
    };
    auto storeA = [&]() {
        char* Sb = (char*)sm + ABASE;
#pragma unroll
        for (int j = 0; j < 4; j++) {
            u32 o = swz((u32)ar * 128u + (u32)((aq * 16 + j * 4) * 2));
            *(uint2*)(Sb + o) = make_uint2(va[j * 2], va[j * 2 + 1]);
        }
    };
    auto loadB = [&](int vc) {
        const uint4* src = ((vc & 1) ? g_Blo : g_Bhi) + (vc >> 1) * 2048;
        u32 dst = sb + BBASE + (u32)(vc % 3) * 32768u;
#pragma unroll
        for (int j = 0; j < 8; j++) {
            int o = j * NTHR + t;
            cpasync16(dst + o * 16, src + o);
        }
        CP_COMMIT();
    };

    loadA(0); storeA(); loadB(0); loadB(1);
    CP_WAIT0();
    __syncthreads();

    float acc[4][4][4];
#pragma unroll
    for (int m = 0; m < 4; m++)
#pragma unroll
        for (int n = 0; n < 4; n++)
#pragma unroll
            for (int q = 0; q < 4; q++) acc[m][n][q] = 0.0f;

#pragma unroll 1
    for (int c = 0; c < NCH; c++) {
        if (2 * c + 2 < VCH) loadB(2 * c + 2);
        if (c + 1 < NCH) loadA(c + 1);

        const u32 Ab  = sb + ABASE;
        const u32 Bhi = sb + BBASE + (u32)((2 * c) % 3) * 32768u;
        const u32 Blo = sb + BBASE + (u32)((2 * c + 1) % 3) * 32768u;
#pragma unroll
        for (int ks = 0; ks < 4; ks++) {
            const u32 kb = (u32)ks * 32u;
            u32 ah[16];
#pragma unroll
            for (int m = 0; m < 4; m++) {
                u32 o = (u32)((m * 16 + (lane & 15)) * 128) + ((u32)(lane >> 4) << 4) + kb;
                ldsm4(Ab + swz(o), ah[m*4+0], ah[m*4+1], ah[m*4+2], ah[m*4+3]);
            }
            u32 bh[8], bl[8];
#pragma unroll
            for (int pr = 0; pr < 2; pr++) {
                u32 o = (u32)((wn0 + pr * 16 + bn) * 128) + kb + bkb;
                ldsm4(Bhi + swz(o), bh[pr*4+0], bh[pr*4+1], bh[pr*4+2], bh[pr*4+3]);
                ldsm4(Blo + swz(o), bl[pr*4+0], bl[pr*4+1], bl[pr*4+2], bl[pr*4+3]);
            }
#pragma unroll
            for (int m = 0; m < 4; m++)
#pragma unroll
                for (int nt = 0; nt < 4; nt++) {
                    float* cc = acc[m][nt];
                    int bi = (nt >> 1) * 4 + (nt & 1) * 2;
                    mma16816h(cc, &ah[m * 4], bh[bi], bh[bi + 1]);
                    mma16816h(cc, &ah[m * 4], bl[bi], bl[bi + 1]);
                }
        }
        if (c + 1 < NCH) {
            __syncthreads();
            storeA();
            loadB(2 * c + 3);
        }
        CP_WAIT0();
        __syncthreads();
    }

    // ================= epilogue =================
    const int g = lane >> 2, tq = (lane & 3) * 2;
    float* prS  = sm + PR_OFF;
    float* pnS  = sm + PN_OFF;
    int*   winS = (int*)(sm + WIN_OFF);

    // stage We2T tiles (pre-swizzled fp16) + proto
    {
        uint4* dh = (uint4*)((char*)sm + W2T_BYTE);
#pragma unroll
        for (int j = 0; j < 4; j++) {
            int o = j * NTHR + t;
            dh[o]        = g_W2Thi[o];
            dh[1024 + o] = g_W2Tlo[o];
        }
        for (int i = t; i < NPROTO * LAT; i += NTHR) prS[i] = proto[i];
    }
    // h = relu(acc + be1) packed to fp16 pairs (C layout == A layout pairs)
    u32 hp01[4][4], hp23[4][4];
#pragma unroll
    for (int m = 0; m < 4; m++)
#pragma unroll
        for (int nt = 0; nt < 4; nt++) {
            int col = wn0 + nt * 8 + tq;
            float b0 = sm[col], b1 = sm[col + 1];
            float* cc = acc[m][nt];
            hp01[m][nt] = pack2h(fmaxf(cc[0] + b0, 0.0f), fmaxf(cc[1] + b1, 0.0f));
            hp23[m][nt] = pack2h(fmaxf(cc[2] + b0, 0.0f), fmaxf(cc[3] + b1, 0.0f));
        }
    __syncthreads();   // We2T + proto staged; B ring dead

    // ---- GEMM2: per-warp K=32 slice, z_partial = h_w @ We2[wn0:wn0+32] ----
    float za[4][4][4];
#pragma unroll
    for (int m = 0; m < 4; m++)
#pragma unroll
        for (int n = 0; n < 4; n++)
#pragma unroll
            for (int q = 0; q < 4; q++) za[m][n][q] = 0.0f;

    const u32 W2h = sb + (u32)W2T_BYTE;
    const u32 W2l = W2h + 16384u;
#pragma unroll
    for (int kt = 0; kt < 2; kt++) {
        int kglob = wn0 + kt * 16;
        u32 tbase = (u32)(kglob >> 6) * 4096u;
        u32 koff  = (u32)((kglob & 63) * 2) + bkb;
        u32 bh[8], bl[8];
#pragma unroll
        for (int pr = 0; pr < 2; pr++) {
            u32 o = (u32)((pr * 16 + bn) * 128) + koff;
            ldsm4(W2h + tbase + swz(o), bh[pr*4+0], bh[pr*4+1], bh[pr*4+2], bh[pr*4+3]);
            ldsm4(W2l + tbase + swz(o), bl[pr*4+0], bl[pr*4+1], bl[pr*4+2], bl[pr*4+3]);
        }
#pragma unroll
        for (int m = 0; m < 4; m++) {
            u32 af[4] = { hp01[m][2*kt], hp23[m][2*kt], hp01[m][2*kt+1], hp23[m][2*kt+1] };
#pragma unroll
            for (int nt = 0; nt < 4; nt++) {
                float* cc = za[m][nt];
                int bi = (nt >> 1) * 4 + (nt & 1) * 2;
                mma16816h(cc, af, bh[bi], bh[bi + 1]);
                mma16816h(cc, af, bl[bi], bl[bi + 1]);
            }
        }
    }
    // store per-warp partials
    {
        float* zp = sm + ZP_OFF + w * BMR * ZSTR;
#pragma unroll
        for (int m = 0; m < 4; m++)
#pragma unroll
            for (int nt = 0; nt < 4; nt++) {
                int row = m * 16 + g, cl = nt * 8 + tq;
                float* cc = za[m][nt];
                zp[row * ZSTR + cl]           = cc[0];
                zp[row * ZSTR + cl + 1]       = cc[1];
                zp[(row + 8) * ZSTR + cl]     = cc[2];
                zp[(row + 8) * ZSTR + cl + 1] = cc[3];
            }
    }
    if (t < NPROTO) {
        const float* pj = prS + t * LAT;
        float a[32];
#pragma unroll
        for (int l = 0; l < 32; l++) a[l] = pj[l] * pj[l];
#pragma unroll
        for (int off = 16; off >= 1; off >>= 1)
#pragma unroll
            for (int i = 0; i < 16; i++)
                if (i < off) a[i] += a[i + off];
        pnS[t] = a[0];
    }
    __syncthreads();

    // ---- reduce 8 warps (k ascending) + be2 -> z ----
    {
        const int r = t >> 2, lb = (t & 3) * 8;
        float zv[8];
#pragma unroll
        for (int l = 0; l < 8; l++) {
            float s = 0.0f;
#pragma unroll
            for (int w2 = 0; w2 < 8; w2++)
                s += sm[ZP_OFF + (w2 * BMR + r) * ZSTR + lb + l];
            zv[l] = s;
        }
        float bz[8];
        *(float4*)bz       = *(const float4*)(be2 + lb);
        *(float4*)(bz + 4) = *(const float4*)(be2 + lb + 4);
#pragma unroll
        for (int l = 0; l < 8; l++) zv[l] += bz[l];
#pragma unroll
        for (int l = 0; l < 8; l++) sm[ZP_OFF + r * ZSTR + lb + l] = zv[l];
        float* out_z = out + (size_t)BATCH * K1;
        *(float4*)(out_z + (row0 + r) * LAT + lb)     = *(float4*)zv;
        *(float4*)(out_z + (row0 + r) * LAT + lb + 4) = *(float4*)(zv + 4);
    }
    __syncthreads();

    // ---- per-row argmin (reference form) + guard ----
    if (t < BMR) {
        const float* zr = sm + ZP_OFF + t * ZSTR;
        float zz = 0.0f;
#pragma unroll
        for (int l = 0; l < LAT; l++) zz = fmaf(zr[l], zr[l], zz);
        float best = 3.4e38f, sec = 3.4e38f;
        int bi = 0;
#pragma unroll 1
        for (int j = 0; j < NPROTO; j++) {
            const float* pj = prS + j * LAT;
            float dot = 0.0f;
#pragma unroll
            for (int l = 0; l < LAT; l++) dot = fmaf(zr[l], pj[l], dot);
            float d = (zz - 2.0f * dot) + pnS[j];
            if (d < best) { sec = best; best = d; bi = j; }
            else if (d < sec) sec = d;
        }
        winS[t] = bi;
        if (sec - best < GUARD) {
            int idx = atomicAdd(&g_repair_count, 1);
            if (idx < BATCH) g_repair_rows[idx] = (int)(row0 + t);
        }
    }
    __syncthreads();

    // ---- som_z + x_recon gather ----
    {
        float* out_som = out + (size_t)BATCH * (K1 + LAT);
        for (int idx = t; idx < BMR * LAT; idx += NTHR) {
            int rr = idx >> 5, l = idx & 31;
            out_som[(row0 + rr) * LAT + l] = prS[winS[rr] * LAT + l];
        }
        const float4* tab = (const float4*)g_recon_table4;
        float4* outr = (float4*)out;
        for (int idx = t; idx < BMR * (K1 / 4); idx += NTHR) {
            int rr = idx / (K1 / 4), q = idx - rr * (K1 / 4);
            outr[(row0 + rr) * (K1 / 4) + q] = tab[winS[rr] * (K1 / 4) + q];
        }
    }
}

// ---------------- repair kernel (identical to R14) ----------------
__global__ void __launch_bounds__(256, 3)
repair_kernel(const float* __restrict__ x,
              const float* __restrict__ We1,
              const float* __restrict__ be1,
              const float* __restrict__ We2,
              const float* __restrict__ be2,
              const float* __restrict__ proto,
              float* __restrict__ out) {
    extern __shared__ float rsm[];
    float* xr   = rsm + RXR;
    float* w1s  = rsm + RW1;
    float* h8   = rsm + RH8;
    float* z8   = rsm + RZ8;
    float* pp   = rsm + RPP;
    float* dd   = rsm + RDD;
    int* rows   = (int*)(rsm + RROWSI);
    int* win8   = (int*)(rsm + RWINI);
    const int t = threadIdx.x;
    const u32 w1b = su(w1s);
    int cnt = g_repair_count;
    if (cnt > BATCH) cnt = BATCH;
    if (blockIdx.x * RROWS >= cnt) return;

    auto issueW1 = [&](int kc) {
        const uint4* s = (const uint4*)(We1 + kc * 16 * HID);
        u32 d = w1b + (u32)(kc & 1) * 16384u;
#pragma unroll
        for (int j = 0; j < 4; j++) cpasync16(d + (u32)(j * 256 + t) * 16u, s + j * 256 + t);
        CP_COMMIT();
    };

    if (t < NPROTO) {
        const float* pj = proto + t * LAT;
        float a[32];
#pragma unroll
        for (int l = 0; l < 32; l++) a[l] = pj[l] * pj[l];
#pragma unroll
        for (int off = 16; off >= 1; off >>= 1)
#pragma unroll
            for (int i = 0; i < 16; i++)
                if (i < off) a[i] += a[i + off];
        pp[t] = a[0];
    }

    for (int g = blockIdx.x; g * RROWS < cnt; g += gridDim.x) {
        const int nr = min(RROWS, cnt - g * RROWS);
        __syncthreads();
        if (t < nr) rows[t] = g_repair_rows[g * RROWS + t];
        __syncthreads();
        issueW1(0);
        for (int i = t; i < nr * (K1 / 4); i += 256) {
            int rr = i / (K1 / 4), q = i - rr * (K1 / 4);
            ((float4*)(xr + rr * K1))[q] = ((const float4*)(x + (size_t)rows[rr] * K1))[q];
        }
        issueW1(1);

        float acc[RROWS];
#pragma unroll
        for (int rr = 0; rr < RROWS; rr++) acc[rr] = 0.0f;

#pragma unroll 1
        for (int kc = 0; kc < 49; kc++) {
            if (kc + 2 <= 48) CP_WAIT1(); else CP_WAIT0();
            __syncthreads();
            const float* wb = w1s + (kc & 1) * 4096;
#pragma unroll 4
            for (int u = 0; u < 16; u++) {
                float wv = wb[u * HID + t];
#pragma unroll
                for (int rr = 0; rr < RROWS; rr++)
                    acc[rr] = fmaf(xr[rr * K1 + kc * 16 + u], wv, acc[rr]);
            }
            __syncthreads();
            if (kc + 2 <= 48) issueW1(kc + 2);
        }
        {
            float b = be1[t];
#pragma unroll
            for (int rr = 0; rr < RROWS; rr++)
                h8[rr * 257 + t] = fmaxf(acc[rr] + b, 0.0f);
        }
        __syncthreads();

        if (t < nr * LAT) {
            int rr = t >> 5, l = t & 31;
            float a = 0.0f;
#pragma unroll 8
            for (int n = 0; n < HID; n++)
                a = fmaf(h8[rr * 257 + n], We2[n * LAT + l], a);
            a += be2[l];
            z8[rr * LAT + l] = a;
            out[(size_t)BATCH * K1 + (size_t)rows[rr] * LAT + l] = a;
        }
        __syncthreads();
        if (t < nr * NPROTO) {
            int rr = t / NPROTO, j = t - rr * NPROTO;
            const float* zr = z8 + rr * LAT;
            const float* pj = proto + j * LAT;
            float zz = 0.0f, dot = 0.0f;
#pragma unroll
            for (int l = 0; l < LAT; l++) zz = fmaf(zr[l], zr[l], zz);
#pragma unroll
            for (int l = 0; l < LAT; l++) dot = fmaf(zr[l], pj[l], dot);
            dd[rr * 32 + j] = (zz - 2.0f * dot) + pp[j];
        }
        __syncthreads();
        if (t < nr) {
            const float* dr = dd + t * 32;
            float best = dr[0];
            int bi = 0;
#pragma unroll
            for (int j = 1; j < NPROTO; j++) {
                float v = dr[j];
                if (v < best) { best = v; bi = j; }
            }
            win8[t] = bi;
        }
        __syncthreads();
        for (int i = t; i < nr * LAT; i += 256) {
            int rr = i >> 5, l = i & 31;
            out[(size_t)BATCH * (K1 + LAT) + (size_t)rows[rr] * LAT + l] =
                proto[win8[rr] * LAT + l];
        }
        const float4* tab = (const float4*)g_recon_table4;
        float4* outr = (float4*)out;
        for (int i = t; i < nr * (K1 / 4); i += 256) {
            int rr = i / (K1 / 4), q = i - rr * (K1 / 4);
            outr[(size_t)rows[rr] * (K1 / 4) + q] = tab[win8[rr] * (K1 / 4) + q];
        }
    }
}

extern "C" void kernel_launch(void* const* d_in, const int* in_sizes, int n_in,
                              void* d_out, int out_size) {
    const float* x    = (const float*)d_in[0];
    const float* We1  = (const float*)d_in[1];
    const float* be1  = (const float*)d_in[2];
    const float* We2  = (const float*)d_in[3];
    const float* be2  = (const float*)d_in[4];
    const float* Wd1  = (const float*)d_in[5];
    const float* bd1  = (const float*)d_in[6];
    const float* Wd2  = (const float*)d_in[7];
    const float* bd2  = (const float*)d_in[8];
    const float* prot = (const float*)d_in[9];
    float* out = (float*)d_out;

    prep_w_kernel<<<NCH, 256>>>(We1);
    prep_we2t_kernel<<<1, 256>>>(We2);
    decoder_table_kernel<<<dim3(NPROTO, 4), 256>>>(Wd1, bd1, Wd2, bd2, prot);

    cudaFuncSetAttribute(dpsom_fused_kernel,
                         cudaFuncAttributeMaxDynamicSharedMemorySize, SMEM_BYTES);
    dpsom_fused_kernel<<<BATCH / BMR, NTHR, SMEM_BYTES>>>(x, be1, be2, prot, out);

    cudaFuncSetAttribute(repair_kernel,
                         cudaFuncAttributeMaxDynamicSharedMemorySize, RSM_BYTES);
    repair_kernel<<<512, 256, RSM_BYTES>>>(x, We1, be1, We2, be2, prot, out);
}